// round 8
// baseline (speedup 1.0000x reference)
#include <cuda_runtime.h>
#include <cuda_fp16.h>
#include <cstdint>
#include <math.h>

// ================= problem constants =================
#define NN    50000
#define EE    400000
#define GG    256
#define FIN   79
#define DD    400
#define BN_EPS 1e-5f

#define NMATS  7
#define WPITCH 416            // staged weight K pitch (halfs)
#define PITCH  416            // activation pitch (fp32 bufs and fp16 planes)
#define XPITCH 96             // layer-1 fp32 pitch (3 * 32)

// ================= scratch (device globals; zero-initialized) ============
__device__ float g_bufA[(size_t)NN * PITCH];
__device__ float g_bufB[(size_t)NN * PITCH];
__device__ float g_xpad[(size_t)NN * XPITCH];
__device__ float g_z1[(size_t)NN * XPITCH];
__device__ __align__(16) __half g_P0hi[(size_t)NN * PITCH];
__device__ __align__(16) __half g_P0lo[(size_t)NN * PITCH];
__device__ __align__(16) __half g_P1hi[(size_t)NN * PITCH];
__device__ __align__(16) __half g_P1lo[(size_t)NN * PITCH];
__device__ __align__(16) __half g_Wh[(size_t)NMATS * DD * WPITCH];
__device__ float g_alpha1[DD], g_beta1[DD], g_alpha2[DD], g_beta2[DD];

// ================= helpers =================
__device__ __forceinline__ uint32_t smem_to_u32(const void* p) {
    uint32_t a;
    asm("{ .reg .u64 t; cvta.to.shared.u64 t, %1; cvt.u32.u64 %0, t; }"
        : "=r"(a) : "l"(p));
    return a;
}

__device__ __forceinline__ void cp16(uint32_t saddr, const void* gptr, bool valid) {
    int sz = valid ? 16 : 0;
    asm volatile("cp.async.cg.shared.global [%0], [%1], 16, %2;"
                 :: "r"(saddr), "l"(gptr), "r"(sz));
}
#define CP_COMMIT() asm volatile("cp.async.commit_group;")
#define CP_WAIT(n)  asm volatile("cp.async.wait_group %0;" :: "n"(n))

#define LDSM4(R, addr) \
    asm volatile("ldmatrix.sync.aligned.m8n8.x4.shared.b16 {%0,%1,%2,%3}, [%4];" \
        : "=r"((R)[0]), "=r"((R)[1]), "=r"((R)[2]), "=r"((R)[3]) : "r"(addr))

#define LDSM2(R, addr) \
    asm volatile("ldmatrix.sync.aligned.m8n8.x2.shared.b16 {%0,%1}, [%2];" \
        : "=r"((R)[0]), "=r"((R)[1]) : "r"(addr))

__device__ __forceinline__ void mma_f16(float* d, const uint32_t* a, const uint32_t* b) {
    asm volatile(
        "mma.sync.aligned.m16n8k16.row.col.f32.f16.f16.f32 "
        "{%0,%1,%2,%3}, {%4,%5,%6,%7}, {%8,%9}, {%0,%1,%2,%3};"
        : "+f"(d[0]), "+f"(d[1]), "+f"(d[2]), "+f"(d[3])
        : "r"(a[0]), "r"(a[1]), "r"(a[2]), "r"(a[3]), "r"(b[0]), "r"(b[1]));
}

__device__ __forceinline__ uint32_t pack_h2(__half x, __half y) {
    return ((uint32_t)*(uint16_t*)&y << 16) | *(uint16_t*)&x;
}

__device__ __forceinline__ void red_add_v4(float* p, float4 v) {
    asm volatile("red.global.add.v4.f32 [%0], {%1, %2, %3, %4};"
                 :: "l"(p), "f"(v.x), "f"(v.y), "f"(v.z), "f"(v.w) : "memory");
}

// ================= fused setup kernel =================
#define T1 (NMATS * DD * WPITCH)
#define SETUP_TOTAL (T1 + 800 + NN * 96)

__global__ void setup_kernel(
    const float* __restrict__ w0, const float* __restrict__ w1,
    const float* __restrict__ w2, const float* __restrict__ w3,
    const float* __restrict__ w4, const float* __restrict__ w5,
    const float* __restrict__ w6,
    const float* __restrict__ b1a, const float* __restrict__ g1,
    const float* __restrict__ bb1, const float* __restrict__ m1,
    const float* __restrict__ v1,
    const float* __restrict__ b1b, const float* __restrict__ g2,
    const float* __restrict__ bb2, const float* __restrict__ m2,
    const float* __restrict__ v2) {
    int idx = blockIdx.x * blockDim.x + threadIdx.x;
    if (idx < T1) {
        const int per_mat = DD * WPITCH;
        int m = idx / per_mat;
        int r = idx - m * per_mat;
        int n = r / WPITCH;
        int k = r - n * WPITCH;
        int Km = (m == 0) ? FIN : DD;
        const float* W;
        switch (m) {
            case 0: W = w0; break; case 1: W = w1; break; case 2: W = w2; break;
            case 3: W = w3; break; case 4: W = w4; break; case 5: W = w5; break;
            default: W = w6; break;
        }
        float val = (k < Km) ? W[(size_t)k * DD + n] : 0.0f;
        g_Wh[idx] = __float2half(val);
    } else if (idx < T1 + 800) {
        int j = idx - T1;
        if (j < DD) {
            float a = g1[j] * rsqrtf(v1[j] + BN_EPS);
            g_alpha1[j] = a;
            g_beta1[j]  = (b1a[j] - m1[j]) * a + bb1[j];
        } else {
            int c = j - DD;
            float a = g2[c] * rsqrtf(v2[c] + BN_EPS);
            g_alpha2[c] = a;
            g_beta2[c]  = (b1b[c] - m2[c]) * a + bb2[c];
        }
    } else if (idx < SETUP_TOTAL) {
        int j = idx - T1 - 800;
        int row = j / 96;
        int t = j - row * 96;
        size_t o = (size_t)row * PITCH + DD + (t & 15);
        int sec = t >> 4;
        switch (sec) {
            case 0: g_bufA[o] = 0.0f; break;
            case 1: g_bufB[o] = 0.0f; break;
            case 2: g_P0hi[o] = __half(0.f); break;
            case 3: g_P0lo[o] = __half(0.f); break;
            case 4: g_P1hi[o] = __half(0.f); break;
            default: g_P1lo[o] = __half(0.f); break;
        }
    }
}

// ================= layer-1 glue =================

__global__ void pad_scale_kernel(const float* __restrict__ x,
                                 const float* __restrict__ eps) {
    int idx = blockIdx.x * blockDim.x + threadIdx.x;
    if (idx >= NN * XPITCH) return;
    int row = idx / XPITCH;
    int col = idx - row * XPITCH;
    float v = (col < FIN) ? x[(size_t)row * FIN + col] : 0.0f;
    g_xpad[idx] = v;
    g_z1[idx]   = (1.0f + eps[0]) * v;
}

__global__ void scatter_add_x_kernel(const int* __restrict__ src,
                                     const int* __restrict__ dst) {
    int idx = blockIdx.x * blockDim.x + threadIdx.x;
    if (idx >= EE * (XPITCH / 4)) return;
    int e = idx / (XPITCH / 4);
    int q = idx - e * (XPITCH / 4);
    const float4 v = *(const float4*)(g_xpad + (size_t)src[e] * XPITCH + q * 4);
    red_add_v4(g_z1 + (size_t)dst[e] * XPITCH + q * 4, v);
}

__global__ void scatter_add4_kernel(const float* __restrict__ h,
                                    const int* __restrict__ src,
                                    const int* __restrict__ dst,
                                    float* __restrict__ z) {
    int idx = blockIdx.x * blockDim.x + threadIdx.x;
    if (idx >= EE * (DD / 4)) return;
    int e = idx / (DD / 4);
    int q = idx - e * (DD / 4);
    const float4 v = *(const float4*)(h + (size_t)src[e] * PITCH + q * 4);
    red_add_v4(z + (size_t)dst[e] * PITCH + q * 4, v);
}

// ================= HMMA GEMM =================
// ASRC 0: A = fp32 (lda pitch), split to fp16 hi/lo in smem.
// ASRC 1: A = pre-split fp16 hi/lo planes (pitch PITCH).
// MODE 0: relu -> fp16 hi/lo output planes. MODE 1: tanh -> fp32 Cf (+Zinit).
// INVARIANT: inputs and outputs must be distinct buffers.
#define BM 128
#define BN 200
#define GTHREADS 640

template <int ASRC>
struct SmemCfg {
    static constexpr int AF = 0;
    static constexpr int AH = (ASRC == 0) ? 18432 : 0;
    static constexpr int AL = AH + 10240;
    static constexpr int BH = AL + 10240;
    static constexpr int STAGE = BH + 16000;
};

template <int ASRC>
__device__ __forceinline__ void load_stage(
    uint32_t sbase,
    const float* __restrict__ Af, int lda,
    const __half* __restrict__ APhi, const __half* __restrict__ APlo,
    const __half* __restrict__ Wh,
    int m0, int n0, int kb, int tid) {
    using C = SmemCfg<ASRC>;
    int k0 = kb * 32;
#pragma unroll 1
    for (int id = tid; id < 1824; id += GTHREADS) {
        if (id < 1024) {
            if (ASRC == 0) {
                int row = id >> 3, ch = id & 7;
                int gr = m0 + row;
                bool valid = gr < NN;
                size_t goff = valid ? ((size_t)gr * lda + k0 + ch * 4) : 0;
                cp16(sbase + C::AF + row * 144 + ch * 16, Af + goff, valid);
            } else {
                int row = id >> 3, ch = id & 7;
                int pl = ch >> 2;       // 0: hi, 1: lo
                int c4 = ch & 3;
                int gr = m0 + row;
                bool valid = gr < NN;
                size_t goff = valid ? ((size_t)gr * PITCH + k0 + c4 * 8) : 0;
                const __half* srcp = pl ? APlo : APhi;
                uint32_t sa = sbase + (pl ? C::AL : C::AH) + row * 80 + c4 * 16;
                cp16(sa, srcp + goff, valid);
            }
        } else {
            int id2 = id - 1024;
            int row = id2 >> 2, ch = id2 & 3;
            size_t goff = (size_t)(n0 + row) * WPITCH + k0 + ch * 8;
            cp16(sbase + C::BH + row * 80 + ch * 16, Wh + goff, true);
        }
    }
}

template <int ASRC>
__device__ __forceinline__ void split_tile(char* sm, int tid) {
    using C = SmemCfg<ASRC>;
    if (tid < 512) {
        int row = tid >> 2, ch = tid & 3;
        const float4 v0 = *(const float4*)(sm + C::AF + row * 144 + ch * 32);
        const float4 v1 = *(const float4*)(sm + C::AF + row * 144 + ch * 32 + 16);
        float f[8] = {v0.x, v0.y, v0.z, v0.w, v1.x, v1.y, v1.z, v1.w};
        uint32_t hp[4], lp[4];
#pragma unroll
        for (int j = 0; j < 4; j++) {
            __half h0 = __float2half(f[2 * j]);
            __half h1 = __float2half(f[2 * j + 1]);
            __half l0 = __float2half(f[2 * j]     - __half2float(h0));
            __half l1 = __float2half(f[2 * j + 1] - __half2float(h1));
            hp[j] = pack_h2(h0, h1);
            lp[j] = pack_h2(l0, l1);
        }
        *(uint4*)(sm + C::AH + row * 80 + ch * 16) = make_uint4(hp[0], hp[1], hp[2], hp[3]);
        *(uint4*)(sm + C::AL + row * 80 + ch * 16) = make_uint4(lp[0], lp[1], lp[2], lp[3]);
    }
}

template <int ASRC, int MODE>
__global__ __launch_bounds__(GTHREADS, 1) void gemm_hmma_kernel(
    const float* __restrict__ Af, int lda,
    const __half* __restrict__ APhi, const __half* __restrict__ APlo,
    int kblks,
    const __half* __restrict__ Wh,
    const float* __restrict__ alpha, const float* __restrict__ beta,
    float* __restrict__ Cf,
    __half* __restrict__ OPhi, __half* __restrict__ OPlo,
    const float* __restrict__ epsn, float* __restrict__ Zinit) {
    using C = SmemCfg<ASRC>;
    extern __shared__ char smem[];
    uint32_t sb = smem_to_u32(smem);
    int tid  = threadIdx.x;
    int wid  = tid >> 5;
    int lane = tid & 31;
    int wm = wid / 5;            // 0..3
    int wn = wid - wm * 5;       // 0..4
    int m0 = blockIdx.x * BM;
    int n0 = blockIdx.y * BN;

    float acc[2][5][4];
#pragma unroll
    for (int i = 0; i < 2; i++)
#pragma unroll
        for (int j = 0; j < 5; j++)
#pragma unroll
            for (int k = 0; k < 4; k++) acc[i][j][k] = 0.0f;

    // prologue: fill stages 0 and 1 (kblks >= 2 always)
    load_stage<ASRC>(sb + 0 * C::STAGE, Af, lda, APhi, APlo, Wh, m0, n0, 0, tid);
    CP_COMMIT();
    load_stage<ASRC>(sb + 1 * C::STAGE, Af, lda, APhi, APlo, Wh, m0, n0, 1, tid);
    CP_COMMIT();

    if (ASRC == 0) {
        CP_WAIT(1);
        __syncthreads();
        split_tile<ASRC>(smem + 0 * C::STAGE, tid);
        __syncthreads();
    }

#pragma unroll 1
    for (int kb = 0; kb < kblks; kb++) {
        int st = kb % 3;
        if (ASRC == 1) {
            if (kb + 1 < kblks) { CP_WAIT(1); } else { CP_WAIT(0); }
            __syncthreads();
        }
        if (kb + 2 < kblks) {
            load_stage<ASRC>(sb + ((kb + 2) % 3) * C::STAGE,
                             Af, lda, APhi, APlo, Wh, m0, n0, kb + 2, tid);
            CP_COMMIT();
        }

        uint32_t sbase = sb + st * C::STAGE;
        // ---- MMA over this k-block (two k=16 slices) ----
#pragma unroll
        for (int kk = 0; kk < 2; kk++) {
            uint32_t af[2][2][4];
#pragma unroll
            for (int mt = 0; mt < 2; mt++) {
                uint32_t row  = wm * 32 + mt * 16 + (lane & 15);
                uint32_t addr = sbase + C::AH + row * 80 + kk * 32 + ((lane >> 4) << 4);
                LDSM4(af[0][mt], addr);
                LDSM4(af[1][mt], addr + (C::AL - C::AH));
            }
            uint32_t bfr[5][2];
#pragma unroll
            for (int nt = 0; nt < 5; nt++) {
                uint32_t row  = wn * 40 + nt * 8 + (lane & 7);
                uint32_t addr = sbase + C::BH + row * 80 + kk * 32 + (((lane >> 3) & 1) << 4);
                LDSM2(bfr[nt], addr);
            }
#pragma unroll
            for (int mt = 0; mt < 2; mt++)
#pragma unroll
                for (int nt = 0; nt < 5; nt++) {
                    mma_f16(acc[mt][nt], af[0][mt], bfr[nt]);
                    mma_f16(acc[mt][nt], af[1][mt], bfr[nt]);
                }
        }

        if (ASRC == 0) {
            if (kb + 1 < kblks) {
                if (kb + 2 < kblks) { CP_WAIT(1); } else { CP_WAIT(0); }
                // barrier AFTER the wait: cp.async data written by other
                // threads must be published before split_tile reads it.
                __syncthreads();
                split_tile<ASRC>(smem + ((kb + 1) % 3) * C::STAGE, tid);
            }
            __syncthreads();
        }
    }

    // ---------------- epilogue ----------------
    float sc = (MODE == 1 && Zinit) ? (1.0f + epsn[0]) : 0.0f;
#pragma unroll
    for (int mt = 0; mt < 2; mt++) {
#pragma unroll
        for (int nt = 0; nt < 5; nt++) {
            int c  = n0 + wn * 40 + nt * 8 + (lane & 3) * 2;
            int r0 = m0 + wm * 32 + mt * 16 + (lane >> 2);
            float a0 = alpha ? alpha[c]     : 1.0f;
            float a1 = alpha ? alpha[c + 1] : 1.0f;
            float b0 = beta[c], b1 = beta[c + 1];
            float v00 = acc[mt][nt][0] * a0 + b0;
            float v01 = acc[mt][nt][1] * a1 + b1;
            float v10 = acc[mt][nt][2] * a0 + b0;
            float v11 = acc[mt][nt][3] * a1 + b1;
            if (MODE == 0) {
                v00 = fmaxf(v00, 0.f); v01 = fmaxf(v01, 0.f);
                v10 = fmaxf(v10, 0.f); v11 = fmaxf(v11, 0.f);
                if (r0 < NN) {
                    __half h0 = __float2half(v00);
                    __half h1 = __float2half(v01);
                    uint32_t hp = pack_h2(h0, h1);
                    uint32_t lp = pack_h2(__float2half(v00 - __half2float(h0)),
                                          __float2half(v01 - __half2float(h1)));
                    size_t o = (size_t)r0 * (PITCH / 2) + (c >> 1);
                    ((uint32_t*)OPhi)[o] = hp;
                    ((uint32_t*)OPlo)[o] = lp;
                }
                if (r0 + 8 < NN) {
                    __half h0 = __float2half(v10);
                    __half h1 = __float2half(v11);
                    uint32_t hp = pack_h2(h0, h1);
                    uint32_t lp = pack_h2(__float2half(v10 - __half2float(h0)),
                                          __float2half(v11 - __half2float(h1)));
                    size_t o = (size_t)(r0 + 8) * (PITCH / 2) + (c >> 1);
                    ((uint32_t*)OPhi)[o] = hp;
                    ((uint32_t*)OPlo)[o] = lp;
                }
            } else {
                float t00 = tanhf(v00), t01 = tanhf(v01);
                float t10 = tanhf(v10), t11 = tanhf(v11);
                if (r0 < NN) {
                    *(float2*)(Cf + (size_t)r0 * PITCH + c) = make_float2(t00, t01);
                    if (Zinit)
                        *(float2*)(Zinit + (size_t)r0 * PITCH + c) =
                            make_float2(sc * t00, sc * t01);
                }
                if (r0 + 8 < NN) {
                    *(float2*)(Cf + (size_t)(r0 + 8) * PITCH + c) = make_float2(t10, t11);
                    if (Zinit)
                        *(float2*)(Zinit + (size_t)(r0 + 8) * PITCH + c) =
                            make_float2(sc * t10, sc * t11);
                }
            }
        }
    }
}

// ================= pooling + final projection (atomic-free) =================

__device__ __forceinline__ int lower_bound_batch(const int* __restrict__ b, int val) {
    int lo = 0, hi = NN;
    while (lo < hi) {
        int mid = (lo + hi) >> 1;
        if (b[mid] < val) lo = mid + 1; else hi = mid;
    }
    return lo;
}

__global__ __launch_bounds__(256) void pool_out_kernel(
    const float* __restrict__ h, const int* __restrict__ batch,
    const float* __restrict__ w, const float* __restrict__ b,
    float* __restrict__ out) {
    int g   = blockIdx.x;
    int tid = threadIdx.x;
    int lo = lower_bound_batch(batch, g);
    int hi = lower_bound_batch(batch, g + 1);
    float invc = 1.0f / fmaxf((float)(hi - lo), 1.0f);
    float part = 0.0f;
    for (int f = tid; f < DD; f += 256) {
        float mx = -INFINITY, sm = 0.0f;
        for (int node = lo; node < hi; node++) {
            float v = h[(size_t)node * PITCH + f];
            mx = fmaxf(mx, v);
            sm += v;
        }
        if (hi == lo) mx = 0.0f;
        part += mx * w[f] + sm * invc * w[DD + f];
    }
#pragma unroll
    for (int o = 16; o > 0; o >>= 1) part += __shfl_down_sync(0xffffffffu, part, o);
    __shared__ float sh[8];
    if ((tid & 31) == 0) sh[tid >> 5] = part;
    __syncthreads();
    if (tid == 0) {
        float t = 0.0f;
#pragma unroll
        for (int i = 0; i < 8; i++) t += sh[i];
        out[g] = t + b[0];
    }
}

// ================= host orchestration =================

static inline int ceil_div(int a, int b) { return (a + b - 1) / b; }

extern "C" void kernel_launch(void* const* d_in, const int* in_sizes, int n_in,
                              void* d_out, int out_size) {
    const float* x     = (const float*)d_in[0];
    const int*   ei    = (const int*)d_in[1];
    const int*   src   = ei;
    const int*   dst   = ei + EE;
    const int*   batch = (const int*)d_in[2];
    int base = (in_sizes[3] == 1) ? 4 : 3;

    const float* mlp1_w1   = (const float*)d_in[base + 0];
    const float* mlp1_b1   = (const float*)d_in[base + 1];
    const float* mlp1_bn_g = (const float*)d_in[base + 2];
    const float* mlp1_bn_b = (const float*)d_in[base + 3];
    const float* mlp1_bn_m = (const float*)d_in[base + 4];
    const float* mlp1_bn_v = (const float*)d_in[base + 5];
    const float* mlp1_w2   = (const float*)d_in[base + 6];
    const float* mlp1_b2   = (const float*)d_in[base + 7];
    const float* mlp2_w1   = (const float*)d_in[base + 8];
    const float* mlp2_b1   = (const float*)d_in[base + 9];
    const float* mlp2_bn_g = (const float*)d_in[base + 10];
    const float* mlp2_bn_b = (const float*)d_in[base + 11];
    const float* mlp2_bn_m = (const float*)d_in[base + 12];
    const float* mlp2_bn_v = (const float*)d_in[base + 13];
    const float* mlp2_w2   = (const float*)d_in[base + 14];
    const float* mlp2_b2   = (const float*)d_in[base + 15];
    const float* out1_w    = (const float*)d_in[base + 16];
    const float* out1_b    = (const float*)d_in[base + 17];
    const float* out2_w    = (const float*)d_in[base + 18];
    const float* out2_b    = (const float*)d_in[base + 19];
    const float* out3_w    = (const float*)d_in[base + 20];
    const float* out3_b    = (const float*)d_in[base + 21];
    const float* out_w     = (const float*)d_in[base + 22];
    const float* out_b     = (const float*)d_in[base + 23];
    const float* eps1      = (const float*)d_in[base + 24];
    const float* eps2      = (const float*)d_in[base + 25];
    const float* eps3      = (const float*)d_in[base + 26];

    float* out = (float*)d_out;

    float *bufA, *bufB, *z1, *alpha1, *beta1, *alpha2, *beta2;
    __half *wh, *p0h, *p0l, *p1h, *p1l;
    cudaGetSymbolAddress((void**)&bufA, g_bufA);
    cudaGetSymbolAddress((void**)&bufB, g_bufB);
    cudaGetSymbolAddress((void**)&z1,   g_z1);
    cudaGetSymbolAddress((void**)&alpha1, g_alpha1);
    cudaGetSymbolAddress((void**)&beta1,  g_beta1);
    cudaGetSymbolAddress((void**)&alpha2, g_alpha2);
    cudaGetSymbolAddress((void**)&beta2,  g_beta2);
    cudaGetSymbolAddress((void**)&wh,  g_Wh);
    cudaGetSymbolAddress((void**)&p0h, g_P0hi);
    cudaGetSymbolAddress((void**)&p0l, g_P0lo);
    cudaGetSymbolAddress((void**)&p1h, g_P1hi);
    cudaGetSymbolAddress((void**)&p1l, g_P1lo);

    const int SMEM0 = 3 * SmemCfg<0>::STAGE;   // 164736
    const int SMEM1 = 3 * SmemCfg<1>::STAGE;   // 109440
    cudaFuncSetAttribute(gemm_hmma_kernel<0, 0>,
                         cudaFuncAttributeMaxDynamicSharedMemorySize, SMEM0);
    cudaFuncSetAttribute(gemm_hmma_kernel<1, 0>,
                         cudaFuncAttributeMaxDynamicSharedMemorySize, SMEM1);
    cudaFuncSetAttribute(gemm_hmma_kernel<1, 1>,
                         cudaFuncAttributeMaxDynamicSharedMemorySize, SMEM1);

    dim3 ggrid(ceil_div(NN, BM), 2);   // (391, 2)
    size_t wmat = (size_t)DD * WPITCH;

    // 1: fused setup
    setup_kernel<<<ceil_div(SETUP_TOTAL, 256), 256>>>(
        mlp1_w1, mlp1_w2, mlp2_w1, mlp2_w2, out1_w, out2_w, out3_w,
        mlp1_b1, mlp1_bn_g, mlp1_bn_b, mlp1_bn_m, mlp1_bn_v,
        mlp2_b1, mlp2_bn_g, mlp2_bn_b, mlp2_bn_m, mlp2_bn_v);

    // ---------- layer 1 ----------
    pad_scale_kernel<<<ceil_div(NN * XPITCH, 256), 256>>>(x, eps1);
    scatter_add_x_kernel<<<ceil_div(EE * (XPITCH / 4), 256), 256>>>(src, dst);
    // g1: fp32 z1 -> relu planes P0
    gemm_hmma_kernel<0, 0><<<ggrid, GTHREADS, SMEM0>>>(
        z1, XPITCH, nullptr, nullptr, 3, wh + 0 * wmat,
        alpha1, beta1, nullptr, p0h, p0l, nullptr, nullptr);
    // g2: P0 -> relu planes P1
    gemm_hmma_kernel<1, 0><<<ggrid, GTHREADS, SMEM1>>>(
        nullptr, 0, p0h, p0l, 13, wh + 1 * wmat,
        nullptr, mlp1_b2, nullptr, p1h, p1l, nullptr, nullptr);
    // g3: P1 -> tanh fp32 bufA, zinit -> bufB
    gemm_hmma_kernel<1, 1><<<ggrid, GTHREADS, SMEM1>>>(
        nullptr, 0, p1h, p1l, 13, wh + 4 * wmat,
        nullptr, out1_b, bufA, nullptr, nullptr, eps2, bufB);
    // ---------- layer 2 ----------
    scatter_add4_kernel<<<ceil_div(EE * (DD / 4), 256), 256>>>(bufA, src, dst, bufB);
    gemm_hmma_kernel<0, 0><<<ggrid, GTHREADS, SMEM0>>>(
        bufB, PITCH, nullptr, nullptr, 13, wh + 2 * wmat,
        alpha2, beta2, nullptr, p0h, p0l, nullptr, nullptr);
    gemm_hmma_kernel<1, 0><<<ggrid, GTHREADS, SMEM1>>>(
        nullptr, 0, p0h, p0l, 13, wh + 3 * wmat,
        nullptr, mlp2_b2, nullptr, p1h, p1l, nullptr, nullptr);
    gemm_hmma_kernel<1, 1><<<ggrid, GTHREADS, SMEM1>>>(
        nullptr, 0, p1h, p1l, 13, wh + 5 * wmat,
        nullptr, out2_b, bufA, nullptr, nullptr, eps3, bufB);
    // ---------- layer 3 ----------
    scatter_add4_kernel<<<ceil_div(EE * (DD / 4), 256), 256>>>(bufA, src, dst, bufB);
    gemm_hmma_kernel<0, 0><<<ggrid, GTHREADS, SMEM0>>>(
        bufB, PITCH, nullptr, nullptr, 13, wh + 2 * wmat,
        alpha2, beta2, nullptr, p0h, p0l, nullptr, nullptr);
    gemm_hmma_kernel<1, 0><<<ggrid, GTHREADS, SMEM1>>>(
        nullptr, 0, p0h, p0l, 13, wh + 3 * wmat,
        nullptr, mlp2_b2, nullptr, p1h, p1l, nullptr, nullptr);
    gemm_hmma_kernel<1, 1><<<ggrid, GTHREADS, SMEM1>>>(
        nullptr, 0, p1h, p1l, 13, wh + 6 * wmat,
        nullptr, out3_b, bufA, nullptr, nullptr, nullptr, nullptr);
    // ---------- pooling + output ----------
    pool_out_kernel<<<GG, 256>>>(bufA, batch, out_w, out_b, out);
    (void)n_in; (void)out_size;
}

// round 9
// speedup vs baseline: 1.0551x; 1.0551x over previous
#include <cuda_runtime.h>
#include <cuda_fp16.h>
#include <cstdint>
#include <math.h>

// ================= problem constants =================
#define NN    50000
#define EE    400000
#define GG    256
#define FIN   79
#define DD    400
#define BN_EPS 1e-5f

#define NMATS  7
#define WPITCH 416            // staged weight K pitch (halfs)
#define PITCH  416            // fp32 activation pitch (13 * 32)
#define XPITCH 96             // layer-1 fp32 pitch (3 * 32)

// ================= scratch (device globals; zero-initialized) ============
__device__ float g_bufA[(size_t)NN * PITCH];
__device__ float g_bufB[(size_t)NN * PITCH];
__device__ float g_bufC[(size_t)NN * PITCH];
__device__ float g_xpad[(size_t)NN * XPITCH];
__device__ float g_z1[(size_t)NN * XPITCH];
__device__ __align__(16) __half g_Wh[(size_t)NMATS * DD * WPITCH];
__device__ float g_alpha1[DD], g_beta1[DD], g_alpha2[DD], g_beta2[DD];

// ================= helpers =================
__device__ __forceinline__ uint32_t smem_to_u32(const void* p) {
    uint32_t a;
    asm("{ .reg .u64 t; cvta.to.shared.u64 t, %1; cvt.u32.u64 %0, t; }"
        : "=r"(a) : "l"(p));
    return a;
}

__device__ __forceinline__ void cp16(uint32_t saddr, const void* gptr, bool valid) {
    int sz = valid ? 16 : 0;
    asm volatile("cp.async.cg.shared.global [%0], [%1], 16, %2;"
                 :: "r"(saddr), "l"(gptr), "r"(sz));
}
#define CP_COMMIT() asm volatile("cp.async.commit_group;")
#define CP_WAIT(n)  asm volatile("cp.async.wait_group %0;" :: "n"(n))

#define LDSM4(R, addr) \
    asm volatile("ldmatrix.sync.aligned.m8n8.x4.shared.b16 {%0,%1,%2,%3}, [%4];" \
        : "=r"((R)[0]), "=r"((R)[1]), "=r"((R)[2]), "=r"((R)[3]) : "r"(addr))

#define LDSM4P(r0, r1, r2, r3, addr) \
    asm volatile("ldmatrix.sync.aligned.m8n8.x4.shared.b16 {%0,%1,%2,%3}, [%4];" \
        : "=r"(r0), "=r"(r1), "=r"(r2), "=r"(r3) : "r"(addr))

#define LDSM2(R, addr) \
    asm volatile("ldmatrix.sync.aligned.m8n8.x2.shared.b16 {%0,%1}, [%2];" \
        : "=r"((R)[0]), "=r"((R)[1]) : "r"(addr))

__device__ __forceinline__ void mma_f16(float* d, const uint32_t* a, const uint32_t* b) {
    asm volatile(
        "mma.sync.aligned.m16n8k16.row.col.f32.f16.f16.f32 "
        "{%0,%1,%2,%3}, {%4,%5,%6,%7}, {%8,%9}, {%0,%1,%2,%3};"
        : "+f"(d[0]), "+f"(d[1]), "+f"(d[2]), "+f"(d[3])
        : "r"(a[0]), "r"(a[1]), "r"(a[2]), "r"(a[3]), "r"(b[0]), "r"(b[1]));
}

__device__ __forceinline__ uint32_t pack_h2(__half x, __half y) {
    return ((uint32_t)*(uint16_t*)&y << 16) | *(uint16_t*)&x;
}

__device__ __forceinline__ void red_add_v4(float* p, float4 v) {
    asm volatile("red.global.add.v4.f32 [%0], {%1, %2, %3, %4};"
                 :: "l"(p), "f"(v.x), "f"(v.y), "f"(v.z), "f"(v.w) : "memory");
}

// ================= fused setup kernel =================
// [0,T1)          : stage W fp16
// [T1,T1+800)     : BN fold
// [.., +NN*48)    : zero pad columns [400,416) of bufA/bufB/bufC
#define T1 (NMATS * DD * WPITCH)
#define SETUP_TOTAL (T1 + 800 + NN * 48)

__global__ void setup_kernel(
    const float* __restrict__ w0, const float* __restrict__ w1,
    const float* __restrict__ w2, const float* __restrict__ w3,
    const float* __restrict__ w4, const float* __restrict__ w5,
    const float* __restrict__ w6,
    const float* __restrict__ b1a, const float* __restrict__ g1,
    const float* __restrict__ bb1, const float* __restrict__ m1,
    const float* __restrict__ v1,
    const float* __restrict__ b1b, const float* __restrict__ g2,
    const float* __restrict__ bb2, const float* __restrict__ m2,
    const float* __restrict__ v2) {
    int idx = blockIdx.x * blockDim.x + threadIdx.x;
    if (idx < T1) {
        const int per_mat = DD * WPITCH;
        int m = idx / per_mat;
        int r = idx - m * per_mat;
        int n = r / WPITCH;
        int k = r - n * WPITCH;
        int Km = (m == 0) ? FIN : DD;
        const float* W;
        switch (m) {
            case 0: W = w0; break; case 1: W = w1; break; case 2: W = w2; break;
            case 3: W = w3; break; case 4: W = w4; break; case 5: W = w5; break;
            default: W = w6; break;
        }
        float val = (k < Km) ? W[(size_t)k * DD + n] : 0.0f;
        g_Wh[idx] = __float2half(val);
    } else if (idx < T1 + 800) {
        int j = idx - T1;
        if (j < DD) {
            float a = g1[j] * rsqrtf(v1[j] + BN_EPS);
            g_alpha1[j] = a;
            g_beta1[j]  = (b1a[j] - m1[j]) * a + bb1[j];
        } else {
            int c = j - DD;
            float a = g2[c] * rsqrtf(v2[c] + BN_EPS);
            g_alpha2[c] = a;
            g_beta2[c]  = (b1b[c] - m2[c]) * a + bb2[c];
        }
    } else if (idx < SETUP_TOTAL) {
        int j = idx - T1 - 800;
        int row = j / 48;
        int t = j - row * 48;
        if (t < 16)      g_bufA[(size_t)row * PITCH + DD + t] = 0.0f;
        else if (t < 32) g_bufB[(size_t)row * PITCH + DD + (t - 16)] = 0.0f;
        else             g_bufC[(size_t)row * PITCH + DD + (t - 32)] = 0.0f;
    }
}

// ================= layer-1 glue =================

__global__ void pad_scale_kernel(const float* __restrict__ x,
                                 const float* __restrict__ eps) {
    int idx = blockIdx.x * blockDim.x + threadIdx.x;
    if (idx >= NN * XPITCH) return;
    int row = idx / XPITCH;
    int col = idx - row * XPITCH;
    float v = (col < FIN) ? x[(size_t)row * FIN + col] : 0.0f;
    g_xpad[idx] = v;
    g_z1[idx]   = (1.0f + eps[0]) * v;
}

__global__ void scatter_add_x_kernel(const int* __restrict__ src,
                                     const int* __restrict__ dst) {
    int idx = blockIdx.x * blockDim.x + threadIdx.x;
    if (idx >= EE * (XPITCH / 4)) return;
    int e = idx / (XPITCH / 4);
    int q = idx - e * (XPITCH / 4);
    const float4 v = *(const float4*)(g_xpad + (size_t)src[e] * XPITCH + q * 4);
    red_add_v4(g_z1 + (size_t)dst[e] * XPITCH + q * 4, v);
}

__global__ void scatter_add4_kernel(const float* __restrict__ h,
                                    const int* __restrict__ src,
                                    const int* __restrict__ dst,
                                    float* __restrict__ z) {
    int idx = blockIdx.x * blockDim.x + threadIdx.x;
    if (idx >= EE * (DD / 4)) return;
    int e = idx / (DD / 4);
    int q = idx - e * (DD / 4);
    const float4 v = *(const float4*)(h + (size_t)src[e] * PITCH + q * 4);
    red_add_v4(z + (size_t)dst[e] * PITCH + q * 4, v);
}

// ================= HMMA GEMM: fp32 A, in-smem fp16 hi/lo split =============
// C[n x 400] = act( alpha .* (A @ W) + beta ); W as single fp16 plane.
// MODE 0: relu -> fp32 Cf.  MODE 1: tanh -> fp32 Cf (+ (1+eps)*tanh -> Zinit)
// INVARIANT: A, Cf, Zinit pairwise distinct.
#define BM 128
#define BN 200
#define GTHREADS 640
#define ST_AF 0                    // fp32 A tile: 128 rows * 144B = 18432
#define ST_AH 18432                // fp16 hi plane: 128 * 80B = 10240
#define ST_AL 28672                // fp16 lo plane: 10240
#define ST_BH 38912                // fp16 W tile: 200 * 80B = 16000
#define STAGE_BYTES 54912
#define GSMEM (3 * STAGE_BYTES)    // 164736 (3-stage)

__device__ __forceinline__ void load_stage(
    uint32_t sbase,
    const float* __restrict__ A, int lda,
    const __half* __restrict__ Wh,
    int m0, int n0, int kb, int tid) {
    int k0 = kb * 32;
#pragma unroll 1
    for (int id = tid; id < 1824; id += GTHREADS) {
        if (id < 1024) {
            int row = id >> 3, ch = id & 7;
            int gr = m0 + row;
            bool valid = gr < NN;
            size_t goff = valid ? ((size_t)gr * lda + k0 + ch * 4) : 0;
            cp16(sbase + ST_AF + row * 144 + ch * 16, A + goff, valid);
        } else {
            int id2 = id - 1024;
            int row = id2 >> 2, ch = id2 & 3;
            size_t goff = (size_t)(n0 + row) * WPITCH + k0 + ch * 8;
            cp16(sbase + ST_BH + row * 80 + ch * 16, Wh + goff, true);
        }
    }
}

__device__ __forceinline__ void split_tile(char* sm, int tid) {
    if (tid < 512) {
        int row = tid >> 2, ch = tid & 3;
        const float4 v0 = *(const float4*)(sm + ST_AF + row * 144 + ch * 32);
        const float4 v1 = *(const float4*)(sm + ST_AF + row * 144 + ch * 32 + 16);
        float f[8] = {v0.x, v0.y, v0.z, v0.w, v1.x, v1.y, v1.z, v1.w};
        uint32_t hp[4], lp[4];
#pragma unroll
        for (int j = 0; j < 4; j++) {
            __half h0 = __float2half(f[2 * j]);
            __half h1 = __float2half(f[2 * j + 1]);
            __half l0 = __float2half(f[2 * j]     - __half2float(h0));
            __half l1 = __float2half(f[2 * j + 1] - __half2float(h1));
            hp[j] = pack_h2(h0, h1);
            lp[j] = pack_h2(l0, l1);
        }
        *(uint4*)(sm + ST_AH + row * 80 + ch * 16) = make_uint4(hp[0], hp[1], hp[2], hp[3]);
        *(uint4*)(sm + ST_AL + row * 80 + ch * 16) = make_uint4(lp[0], lp[1], lp[2], lp[3]);
    }
}

template <int MODE>
__global__ __launch_bounds__(GTHREADS, 1) void gemm_hmma_kernel(
    const float* __restrict__ A, int lda, int kblks,
    const __half* __restrict__ Wh,
    const float* __restrict__ alpha, const float* __restrict__ beta,
    float* __restrict__ Cf,
    const float* __restrict__ epsn, float* __restrict__ Zinit) {
    extern __shared__ char smem[];
    uint32_t sb = smem_to_u32(smem);
    int tid  = threadIdx.x;
    int wid  = tid >> 5;
    int lane = tid & 31;
    int wm = wid / 5;            // 0..3
    int wn = wid - wm * 5;       // 0..4
    int m0 = blockIdx.x * BM;
    int n0 = blockIdx.y * BN;

    float acc[2][5][4];
#pragma unroll
    for (int i = 0; i < 2; i++)
#pragma unroll
        for (int j = 0; j < 5; j++)
#pragma unroll
            for (int k = 0; k < 4; k++) acc[i][j][k] = 0.0f;

    // prologue: fill stages 0 and 1; split stage 0 (kblks >= 2 always)
    load_stage(sb + 0 * STAGE_BYTES, A, lda, Wh, m0, n0, 0, tid);
    CP_COMMIT();
    load_stage(sb + 1 * STAGE_BYTES, A, lda, Wh, m0, n0, 1, tid);
    CP_COMMIT();
    CP_WAIT(1);
    __syncthreads();
    split_tile(smem + 0 * STAGE_BYTES, tid);
    __syncthreads();

#pragma unroll 1
    for (int kb = 0; kb < kblks; kb++) {
        if (kb + 2 < kblks) {
            load_stage(sb + ((kb + 2) % 3) * STAGE_BYTES, A, lda, Wh, m0, n0, kb + 2, tid);
            CP_COMMIT();
        }

        uint32_t sbase = sb + (kb % 3) * STAGE_BYTES;
#pragma unroll
        for (int kk = 0; kk < 2; kk++) {
            uint32_t af[2][2][4];   // [plane][mtile][4]
#pragma unroll
            for (int mt = 0; mt < 2; mt++) {
                uint32_t row  = wm * 32 + mt * 16 + (lane & 15);
                uint32_t addr = sbase + ST_AH + row * 80 + kk * 32 + ((lane >> 4) << 4);
                LDSM4(af[0][mt], addr);
                LDSM4(af[1][mt], addr + (ST_AL - ST_AH));
            }
            uint32_t bfr[5][2];
            {
                // nt pairs (0,1) and (2,3) via LDSM4; nt=4 via LDSM2
                int l8  = lane & 7;
                int grp = lane >> 3;           // 0..3
#pragma unroll
                for (int pr = 0; pr < 2; pr++) {
                    uint32_t rowB = wn * 40 + pr * 16 + (grp >> 1) * 8 + l8;
                    uint32_t addr = sbase + ST_BH + rowB * 80 + kk * 32 + ((grp & 1) << 4);
                    LDSM4P(bfr[2 * pr][0], bfr[2 * pr][1],
                           bfr[2 * pr + 1][0], bfr[2 * pr + 1][1], addr);
                }
                uint32_t rowB = wn * 40 + 32 + l8;
                uint32_t addr = sbase + ST_BH + rowB * 80 + kk * 32 + (((lane >> 3) & 1) << 4);
                LDSM2(bfr[4], addr);
            }
#pragma unroll
            for (int mt = 0; mt < 2; mt++)
#pragma unroll
                for (int nt = 0; nt < 5; nt++) {
                    mma_f16(acc[mt][nt], af[0][mt], bfr[nt]);  // Ah * W
                    mma_f16(acc[mt][nt], af[1][mt], bfr[nt]);  // Al * W
                }
        }

        if (kb + 1 < kblks) {
            if (kb + 2 < kblks) { CP_WAIT(1); } else { CP_WAIT(0); }
            // barrier AFTER the wait: cp.async data written by other threads
            // must be published before split_tile reads it.
            __syncthreads();
            split_tile(smem + ((kb + 1) % 3) * STAGE_BYTES, tid);
        }
        __syncthreads();
    }

    // ---------------- epilogue ----------------
    float sc = (MODE == 1 && Zinit) ? (1.0f + epsn[0]) : 0.0f;
#pragma unroll
    for (int mt = 0; mt < 2; mt++) {
#pragma unroll
        for (int nt = 0; nt < 5; nt++) {
            int c  = n0 + wn * 40 + nt * 8 + (lane & 3) * 2;
            int r0 = m0 + wm * 32 + mt * 16 + (lane >> 2);
            float a0 = alpha ? alpha[c]     : 1.0f;
            float a1 = alpha ? alpha[c + 1] : 1.0f;
            float b0 = beta[c], b1 = beta[c + 1];
            float v00 = acc[mt][nt][0] * a0 + b0;
            float v01 = acc[mt][nt][1] * a1 + b1;
            float v10 = acc[mt][nt][2] * a0 + b0;
            float v11 = acc[mt][nt][3] * a1 + b1;
            if (MODE == 0) {
                if (r0 < NN)
                    *(float2*)(Cf + (size_t)r0 * PITCH + c) =
                        make_float2(fmaxf(v00, 0.f), fmaxf(v01, 0.f));
                if (r0 + 8 < NN)
                    *(float2*)(Cf + (size_t)(r0 + 8) * PITCH + c) =
                        make_float2(fmaxf(v10, 0.f), fmaxf(v11, 0.f));
            } else {
                float t00 = tanhf(v00), t01 = tanhf(v01);
                float t10 = tanhf(v10), t11 = tanhf(v11);
                if (r0 < NN) {
                    *(float2*)(Cf + (size_t)r0 * PITCH + c) = make_float2(t00, t01);
                    if (Zinit)
                        *(float2*)(Zinit + (size_t)r0 * PITCH + c) =
                            make_float2(sc * t00, sc * t01);
                }
                if (r0 + 8 < NN) {
                    *(float2*)(Cf + (size_t)(r0 + 8) * PITCH + c) = make_float2(t10, t11);
                    if (Zinit)
                        *(float2*)(Zinit + (size_t)(r0 + 8) * PITCH + c) =
                            make_float2(sc * t10, sc * t11);
                }
            }
        }
    }
}

// ================= pooling + final projection (atomic-free) =================

__device__ __forceinline__ int lower_bound_batch(const int* __restrict__ b, int val) {
    int lo = 0, hi = NN;
    while (lo < hi) {
        int mid = (lo + hi) >> 1;
        if (b[mid] < val) lo = mid + 1; else hi = mid;
    }
    return lo;
}

__global__ __launch_bounds__(256) void pool_out_kernel(
    const float* __restrict__ h, const int* __restrict__ batch,
    const float* __restrict__ w, const float* __restrict__ b,
    float* __restrict__ out) {
    int g   = blockIdx.x;
    int tid = threadIdx.x;
    int lo = lower_bound_batch(batch, g);
    int hi = lower_bound_batch(batch, g + 1);
    float invc = 1.0f / fmaxf((float)(hi - lo), 1.0f);
    float part = 0.0f;
    for (int f = tid; f < DD; f += 256) {
        float mx = -INFINITY, sm = 0.0f;
        for (int node = lo; node < hi; node++) {
            float v = h[(size_t)node * PITCH + f];
            mx = fmaxf(mx, v);
            sm += v;
        }
        if (hi == lo) mx = 0.0f;
        part += mx * w[f] + sm * invc * w[DD + f];
    }
#pragma unroll
    for (int o = 16; o > 0; o >>= 1) part += __shfl_down_sync(0xffffffffu, part, o);
    __shared__ float sh[8];
    if ((tid & 31) == 0) sh[tid >> 5] = part;
    __syncthreads();
    if (tid == 0) {
        float t = 0.0f;
#pragma unroll
        for (int i = 0; i < 8; i++) t += sh[i];
        out[g] = t + b[0];
    }
}

// ================= host orchestration =================

static inline int ceil_div(int a, int b) { return (a + b - 1) / b; }

extern "C" void kernel_launch(void* const* d_in, const int* in_sizes, int n_in,
                              void* d_out, int out_size) {
    const float* x     = (const float*)d_in[0];
    const int*   ei    = (const int*)d_in[1];
    const int*   src   = ei;
    const int*   dst   = ei + EE;
    const int*   batch = (const int*)d_in[2];
    int base = (in_sizes[3] == 1) ? 4 : 3;

    const float* mlp1_w1   = (const float*)d_in[base + 0];
    const float* mlp1_b1   = (const float*)d_in[base + 1];
    const float* mlp1_bn_g = (const float*)d_in[base + 2];
    const float* mlp1_bn_b = (const float*)d_in[base + 3];
    const float* mlp1_bn_m = (const float*)d_in[base + 4];
    const float* mlp1_bn_v = (const float*)d_in[base + 5];
    const float* mlp1_w2   = (const float*)d_in[base + 6];
    const float* mlp1_b2   = (const float*)d_in[base + 7];
    const float* mlp2_w1   = (const float*)d_in[base + 8];
    const float* mlp2_b1   = (const float*)d_in[base + 9];
    const float* mlp2_bn_g = (const float*)d_in[base + 10];
    const float* mlp2_bn_b = (const float*)d_in[base + 11];
    const float* mlp2_bn_m = (const float*)d_in[base + 12];
    const float* mlp2_bn_v = (const float*)d_in[base + 13];
    const float* mlp2_w2   = (const float*)d_in[base + 14];
    const float* mlp2_b2   = (const float*)d_in[base + 15];
    const float* out1_w    = (const float*)d_in[base + 16];
    const float* out1_b    = (const float*)d_in[base + 17];
    const float* out2_w    = (const float*)d_in[base + 18];
    const float* out2_b    = (const float*)d_in[base + 19];
    const float* out3_w    = (const float*)d_in[base + 20];
    const float* out3_b    = (const float*)d_in[base + 21];
    const float* out_w     = (const float*)d_in[base + 22];
    const float* out_b     = (const float*)d_in[base + 23];
    const float* eps1      = (const float*)d_in[base + 24];
    const float* eps2      = (const float*)d_in[base + 25];
    const float* eps3      = (const float*)d_in[base + 26];

    float* out = (float*)d_out;

    float *bufA, *bufB, *bufC, *z1, *alpha1, *beta1, *alpha2, *beta2;
    __half* wh;
    cudaGetSymbolAddress((void**)&bufA, g_bufA);
    cudaGetSymbolAddress((void**)&bufB, g_bufB);
    cudaGetSymbolAddress((void**)&bufC, g_bufC);
    cudaGetSymbolAddress((void**)&z1,   g_z1);
    cudaGetSymbolAddress((void**)&alpha1, g_alpha1);
    cudaGetSymbolAddress((void**)&beta1,  g_beta1);
    cudaGetSymbolAddress((void**)&alpha2, g_alpha2);
    cudaGetSymbolAddress((void**)&beta2,  g_beta2);
    cudaGetSymbolAddress((void**)&wh, g_Wh);

    cudaFuncSetAttribute(gemm_hmma_kernel<0>,
                         cudaFuncAttributeMaxDynamicSharedMemorySize, GSMEM);
    cudaFuncSetAttribute(gemm_hmma_kernel<1>,
                         cudaFuncAttributeMaxDynamicSharedMemorySize, GSMEM);

    dim3 ggrid(ceil_div(NN, BM), 2);   // (391, 2)
    size_t wmat = (size_t)DD * WPITCH;

    // 1: fused setup
    setup_kernel<<<ceil_div(SETUP_TOTAL, 256), 256>>>(
        mlp1_w1, mlp1_w2, mlp2_w1, mlp2_w2, out1_w, out2_w, out3_w,
        mlp1_b1, mlp1_bn_g, mlp1_bn_b, mlp1_bn_m, mlp1_bn_v,
        mlp2_b1, mlp2_bn_g, mlp2_bn_b, mlp2_bn_m, mlp2_bn_v);

    // ---------- layer 1 ----------
    pad_scale_kernel<<<ceil_div(NN * XPITCH, 256), 256>>>(x, eps1);
    scatter_add_x_kernel<<<ceil_div(EE * (XPITCH / 4), 256), 256>>>(src, dst);
    gemm_hmma_kernel<0><<<ggrid, GTHREADS, GSMEM>>>(z1, XPITCH, 3, wh + 0 * wmat,
                                                    alpha1, beta1, bufA, nullptr, nullptr);
    gemm_hmma_kernel<0><<<ggrid, GTHREADS, GSMEM>>>(bufA, PITCH, 13, wh + 1 * wmat,
                                                    nullptr, mlp1_b2, bufB, nullptr, nullptr);
    // tanh: h1 -> bufA, (1+eps2)*h1 -> bufC
    gemm_hmma_kernel<1><<<ggrid, GTHREADS, GSMEM>>>(bufB, PITCH, 13, wh + 4 * wmat,
                                                    nullptr, out1_b, bufA, eps2, bufC);
    // ---------- layer 2 ----------
    scatter_add4_kernel<<<ceil_div(EE * (DD / 4), 256), 256>>>(bufA, src, dst, bufC);
    gemm_hmma_kernel<0><<<ggrid, GTHREADS, GSMEM>>>(bufC, PITCH, 13, wh + 2 * wmat,
                                                    alpha2, beta2, bufB, nullptr, nullptr);
    gemm_hmma_kernel<0><<<ggrid, GTHREADS, GSMEM>>>(bufB, PITCH, 13, wh + 3 * wmat,
                                                    nullptr, mlp2_b2, bufA, nullptr, nullptr);
    // tanh: h2 -> bufB, (1+eps3)*h2 -> bufC
    gemm_hmma_kernel<1><<<ggrid, GTHREADS, GSMEM>>>(bufA, PITCH, 13, wh + 5 * wmat,
                                                    nullptr, out2_b, bufB, eps3, bufC);
    // ---------- layer 3 ----------
    scatter_add4_kernel<<<ceil_div(EE * (DD / 4), 256), 256>>>(bufB, src, dst, bufC);
    gemm_hmma_kernel<0><<<ggrid, GTHREADS, GSMEM>>>(bufC, PITCH, 13, wh + 2 * wmat,
                                                    alpha2, beta2, bufA, nullptr, nullptr);
    gemm_hmma_kernel<0><<<ggrid, GTHREADS, GSMEM>>>(bufA, PITCH, 13, wh + 3 * wmat,
                                                    nullptr, mlp2_b2, bufB, nullptr, nullptr);
    gemm_hmma_kernel<1><<<ggrid, GTHREADS, GSMEM>>>(bufB, PITCH, 13, wh + 6 * wmat,
                                                    nullptr, out3_b, bufA, nullptr, nullptr);
    // ---------- pooling + output ----------
    pool_out_kernel<<<GG, 256>>>(bufA, batch, out_w, out_b, out);
    (void)n_in; (void)out_size;
}

// round 10
// speedup vs baseline: 1.2080x; 1.1449x over previous
#include <cuda_runtime.h>
#include <cuda_fp16.h>
#include <cstdint>
#include <math.h>

// ================= problem constants =================
#define NN    50000
#define EE    400000
#define GG    256
#define FIN   79
#define DD    400
#define BN_EPS 1e-5f

#define NMATS  7
#define WPITCH 416            // staged weight K pitch (halfs)
#define PITCH  416            // fp32 activation pitch (13 * 32)
#define XPITCH 96             // layer-1 fp32 pitch (3 * 32)

// ================= scratch (device globals; zero-initialized) ============
__device__ float g_bufA[(size_t)NN * PITCH];
__device__ float g_bufB[(size_t)NN * PITCH];
__device__ float g_bufC[(size_t)NN * PITCH];
__device__ float g_xpad[(size_t)NN * XPITCH];
__device__ float g_z1[(size_t)NN * XPITCH];
__device__ __align__(16) __half g_Wh[(size_t)NMATS * DD * WPITCH];
__device__ float g_alpha1[DD], g_beta1[DD], g_alpha2[DD], g_beta2[DD];

// ================= helpers =================
__device__ __forceinline__ uint32_t smem_to_u32(const void* p) {
    uint32_t a;
    asm("{ .reg .u64 t; cvta.to.shared.u64 t, %1; cvt.u32.u64 %0, t; }"
        : "=r"(a) : "l"(p));
    return a;
}

__device__ __forceinline__ void cp16(uint32_t saddr, const void* gptr, bool valid) {
    int sz = valid ? 16 : 0;
    asm volatile("cp.async.cg.shared.global [%0], [%1], 16, %2;"
                 :: "r"(saddr), "l"(gptr), "r"(sz));
}
#define CP_COMMIT() asm volatile("cp.async.commit_group;")
#define CP_WAIT(n)  asm volatile("cp.async.wait_group %0;" :: "n"(n))

#define LDSM4(R, addr) \
    asm volatile("ldmatrix.sync.aligned.m8n8.x4.shared.b16 {%0,%1,%2,%3}, [%4];" \
        : "=r"((R)[0]), "=r"((R)[1]), "=r"((R)[2]), "=r"((R)[3]) : "r"(addr))

#define LDSM4P(r0, r1, r2, r3, addr) \
    asm volatile("ldmatrix.sync.aligned.m8n8.x4.shared.b16 {%0,%1,%2,%3}, [%4];" \
        : "=r"(r0), "=r"(r1), "=r"(r2), "=r"(r3) : "r"(addr))

#define LDSM2(R, addr) \
    asm volatile("ldmatrix.sync.aligned.m8n8.x2.shared.b16 {%0,%1}, [%2];" \
        : "=r"((R)[0]), "=r"((R)[1]) : "r"(addr))

__device__ __forceinline__ void mma_f16(float* d, const uint32_t* a, const uint32_t* b) {
    asm volatile(
        "mma.sync.aligned.m16n8k16.row.col.f32.f16.f16.f32 "
        "{%0,%1,%2,%3}, {%4,%5,%6,%7}, {%8,%9}, {%0,%1,%2,%3};"
        : "+f"(d[0]), "+f"(d[1]), "+f"(d[2]), "+f"(d[3])
        : "r"(a[0]), "r"(a[1]), "r"(a[2]), "r"(a[3]), "r"(b[0]), "r"(b[1]));
}

__device__ __forceinline__ uint32_t pack_h2(__half x, __half y) {
    return ((uint32_t)*(uint16_t*)&y << 16) | *(uint16_t*)&x;
}

__device__ __forceinline__ void red_add_v4(float* p, float4 v) {
    asm volatile("red.global.add.v4.f32 [%0], {%1, %2, %3, %4};"
                 :: "l"(p), "f"(v.x), "f"(v.y), "f"(v.z), "f"(v.w) : "memory");
}

// ================= fused setup kernel =================
#define T1 (NMATS * DD * WPITCH)
#define SETUP_TOTAL (T1 + 800 + NN * 48)

__global__ void setup_kernel(
    const float* __restrict__ w0, const float* __restrict__ w1,
    const float* __restrict__ w2, const float* __restrict__ w3,
    const float* __restrict__ w4, const float* __restrict__ w5,
    const float* __restrict__ w6,
    const float* __restrict__ b1a, const float* __restrict__ g1,
    const float* __restrict__ bb1, const float* __restrict__ m1,
    const float* __restrict__ v1,
    const float* __restrict__ b1b, const float* __restrict__ g2,
    const float* __restrict__ bb2, const float* __restrict__ m2,
    const float* __restrict__ v2) {
    int idx = blockIdx.x * blockDim.x + threadIdx.x;
    if (idx < T1) {
        const int per_mat = DD * WPITCH;
        int m = idx / per_mat;
        int r = idx - m * per_mat;
        int n = r / WPITCH;
        int k = r - n * WPITCH;
        int Km = (m == 0) ? FIN : DD;
        const float* W;
        switch (m) {
            case 0: W = w0; break; case 1: W = w1; break; case 2: W = w2; break;
            case 3: W = w3; break; case 4: W = w4; break; case 5: W = w5; break;
            default: W = w6; break;
        }
        float val = (k < Km) ? W[(size_t)k * DD + n] : 0.0f;
        g_Wh[idx] = __float2half(val);
    } else if (idx < T1 + 800) {
        int j = idx - T1;
        if (j < DD) {
            float a = g1[j] * rsqrtf(v1[j] + BN_EPS);
            g_alpha1[j] = a;
            g_beta1[j]  = (b1a[j] - m1[j]) * a + bb1[j];
        } else {
            int c = j - DD;
            float a = g2[c] * rsqrtf(v2[c] + BN_EPS);
            g_alpha2[c] = a;
            g_beta2[c]  = (b1b[c] - m2[c]) * a + bb2[c];
        }
    } else if (idx < SETUP_TOTAL) {
        int j = idx - T1 - 800;
        int row = j / 48;
        int t = j - row * 48;
        if (t < 16)      g_bufA[(size_t)row * PITCH + DD + t] = 0.0f;
        else if (t < 32) g_bufB[(size_t)row * PITCH + DD + (t - 16)] = 0.0f;
        else             g_bufC[(size_t)row * PITCH + DD + (t - 32)] = 0.0f;
    }
}

// ================= layer-1 glue =================

__global__ void pad_scale_kernel(const float* __restrict__ x,
                                 const float* __restrict__ eps) {
    int idx = blockIdx.x * blockDim.x + threadIdx.x;
    if (idx >= NN * XPITCH) return;
    int row = idx / XPITCH;
    int col = idx - row * XPITCH;
    float v = (col < FIN) ? x[(size_t)row * FIN + col] : 0.0f;
    g_xpad[idx] = v;
    g_z1[idx]   = (1.0f + eps[0]) * v;
}

__global__ void scatter_add_x_kernel(const int* __restrict__ src,
                                     const int* __restrict__ dst) {
    int idx = blockIdx.x * blockDim.x + threadIdx.x;
    if (idx >= EE * (XPITCH / 4)) return;
    int e = idx / (XPITCH / 4);
    int q = idx - e * (XPITCH / 4);
    const float4 v = *(const float4*)(g_xpad + (size_t)src[e] * XPITCH + q * 4);
    red_add_v4(g_z1 + (size_t)dst[e] * XPITCH + q * 4, v);
}

__global__ void scatter_add4_kernel(const float* __restrict__ h,
                                    const int* __restrict__ src,
                                    const int* __restrict__ dst,
                                    float* __restrict__ z) {
    int idx = blockIdx.x * blockDim.x + threadIdx.x;
    if (idx >= EE * (DD / 4)) return;
    int e = idx / (DD / 4);
    int q = idx - e * (DD / 4);
    const float4 v = *(const float4*)(h + (size_t)src[e] * PITCH + q * 4);
    red_add_v4(z + (size_t)dst[e] * PITCH + q * 4, v);
}

// ================= HMMA GEMM: fp32 A, in-smem fp16 hi/lo split =============
// BM=64, 320 threads, 2 CTAs/SM (occupancy play).
// C[n x 400] = act( alpha .* (A @ W) + beta ); W as single fp16 plane.
// MODE 0: relu -> fp32 Cf.  MODE 1: tanh -> fp32 Cf (+ (1+eps)*tanh -> Zinit)
// INVARIANT: A, Cf, Zinit pairwise distinct.
#define BM 64
#define BN 200
#define GTHREADS 320
#define ST_AF 0                    // fp32 A tile: 64 rows * 144B = 9216
#define ST_AH 9216                 // fp16 hi plane: 64 * 80B = 5120
#define ST_AL 14336                // fp16 lo plane: 5120
#define ST_BH 19456                // fp16 W tile: 200 * 80B = 16000
#define STAGE_BYTES 35456
#define GSMEM (3 * STAGE_BYTES)    // 106368 (3-stage; 2 CTAs = 212736 < 228K)

__device__ __forceinline__ void load_stage(
    uint32_t sbase,
    const float* __restrict__ A, int lda,
    const __half* __restrict__ Wh,
    int m0, int n0, int kb, int tid) {
    int k0 = kb * 32;
#pragma unroll 1
    for (int id = tid; id < 1312; id += GTHREADS) {
        if (id < 512) {
            int row = id >> 3, ch = id & 7;
            int gr = m0 + row;
            bool valid = gr < NN;
            size_t goff = valid ? ((size_t)gr * lda + k0 + ch * 4) : 0;
            cp16(sbase + ST_AF + row * 144 + ch * 16, A + goff, valid);
        } else {
            int id2 = id - 512;
            int row = id2 >> 2, ch = id2 & 3;
            size_t goff = (size_t)(n0 + row) * WPITCH + k0 + ch * 8;
            cp16(sbase + ST_BH + row * 80 + ch * 16, Wh + goff, true);
        }
    }
}

__device__ __forceinline__ void split_tile(char* sm, int tid) {
    if (tid < 256) {
        int row = tid >> 2, ch = tid & 3;
        const float4 v0 = *(const float4*)(sm + ST_AF + row * 144 + ch * 32);
        const float4 v1 = *(const float4*)(sm + ST_AF + row * 144 + ch * 32 + 16);
        float f[8] = {v0.x, v0.y, v0.z, v0.w, v1.x, v1.y, v1.z, v1.w};
        uint32_t hp[4], lp[4];
#pragma unroll
        for (int j = 0; j < 4; j++) {
            __half h0 = __float2half(f[2 * j]);
            __half h1 = __float2half(f[2 * j + 1]);
            __half l0 = __float2half(f[2 * j]     - __half2float(h0));
            __half l1 = __float2half(f[2 * j + 1] - __half2float(h1));
            hp[j] = pack_h2(h0, h1);
            lp[j] = pack_h2(l0, l1);
        }
        *(uint4*)(sm + ST_AH + row * 80 + ch * 16) = make_uint4(hp[0], hp[1], hp[2], hp[3]);
        *(uint4*)(sm + ST_AL + row * 80 + ch * 16) = make_uint4(lp[0], lp[1], lp[2], lp[3]);
    }
}

template <int MODE>
__global__ __launch_bounds__(GTHREADS, 2) void gemm_hmma_kernel(
    const float* __restrict__ A, int lda, int kblks,
    const __half* __restrict__ Wh,
    const float* __restrict__ alpha, const float* __restrict__ beta,
    float* __restrict__ Cf,
    const float* __restrict__ epsn, float* __restrict__ Zinit) {
    extern __shared__ char smem[];
    uint32_t sb = smem_to_u32(smem);
    int tid  = threadIdx.x;
    int wid  = tid >> 5;
    int lane = tid & 31;
    int wm = wid / 5;            // 0..1
    int wn = wid - wm * 5;       // 0..4
    int m0 = blockIdx.x * BM;
    int n0 = blockIdx.y * BN;

    float acc[2][5][4];
#pragma unroll
    for (int i = 0; i < 2; i++)
#pragma unroll
        for (int j = 0; j < 5; j++)
#pragma unroll
            for (int k = 0; k < 4; k++) acc[i][j][k] = 0.0f;

    // prologue: fill stages 0 and 1; split stage 0 (kblks >= 2 always)
    load_stage(sb + 0 * STAGE_BYTES, A, lda, Wh, m0, n0, 0, tid);
    CP_COMMIT();
    load_stage(sb + 1 * STAGE_BYTES, A, lda, Wh, m0, n0, 1, tid);
    CP_COMMIT();
    CP_WAIT(1);
    __syncthreads();
    split_tile(smem + 0 * STAGE_BYTES, tid);
    __syncthreads();

#pragma unroll 1
    for (int kb = 0; kb < kblks; kb++) {
        if (kb + 2 < kblks) {
            load_stage(sb + ((kb + 2) % 3) * STAGE_BYTES, A, lda, Wh, m0, n0, kb + 2, tid);
            CP_COMMIT();
        }

        uint32_t sbase = sb + (kb % 3) * STAGE_BYTES;
#pragma unroll
        for (int kk = 0; kk < 2; kk++) {
            uint32_t af[2][2][4];   // [plane][mtile][4]
#pragma unroll
            for (int mt = 0; mt < 2; mt++) {
                uint32_t row  = wm * 32 + mt * 16 + (lane & 15);
                uint32_t addr = sbase + ST_AH + row * 80 + kk * 32 + ((lane >> 4) << 4);
                LDSM4(af[0][mt], addr);
                LDSM4(af[1][mt], addr + (ST_AL - ST_AH));
            }
            uint32_t bfr[5][2];
            {
                int l8  = lane & 7;
                int grp = lane >> 3;           // 0..3
#pragma unroll
                for (int pr = 0; pr < 2; pr++) {
                    uint32_t rowB = wn * 40 + pr * 16 + (grp >> 1) * 8 + l8;
                    uint32_t addr = sbase + ST_BH + rowB * 80 + kk * 32 + ((grp & 1) << 4);
                    LDSM4P(bfr[2 * pr][0], bfr[2 * pr][1],
                           bfr[2 * pr + 1][0], bfr[2 * pr + 1][1], addr);
                }
                uint32_t rowB = wn * 40 + 32 + l8;
                uint32_t addr = sbase + ST_BH + rowB * 80 + kk * 32 + (((lane >> 3) & 1) << 4);
                LDSM2(bfr[4], addr);
            }
#pragma unroll
            for (int mt = 0; mt < 2; mt++)
#pragma unroll
                for (int nt = 0; nt < 5; nt++) {
                    mma_f16(acc[mt][nt], af[0][mt], bfr[nt]);  // Ah * W
                    mma_f16(acc[mt][nt], af[1][mt], bfr[nt]);  // Al * W
                }
        }

        if (kb + 1 < kblks) {
            if (kb + 2 < kblks) { CP_WAIT(1); } else { CP_WAIT(0); }
            __syncthreads();   // publish cp.async data before split reads it
            split_tile(smem + ((kb + 1) % 3) * STAGE_BYTES, tid);
        }
        __syncthreads();
    }

    // ---------------- epilogue ----------------
    float sc = (MODE == 1 && Zinit) ? (1.0f + epsn[0]) : 0.0f;
#pragma unroll
    for (int mt = 0; mt < 2; mt++) {
#pragma unroll
        for (int nt = 0; nt < 5; nt++) {
            int c  = n0 + wn * 40 + nt * 8 + (lane & 3) * 2;
            int r0 = m0 + wm * 32 + mt * 16 + (lane >> 2);
            float a0 = alpha ? alpha[c]     : 1.0f;
            float a1 = alpha ? alpha[c + 1] : 1.0f;
            float b0 = beta[c], b1 = beta[c + 1];
            float v00 = acc[mt][nt][0] * a0 + b0;
            float v01 = acc[mt][nt][1] * a1 + b1;
            float v10 = acc[mt][nt][2] * a0 + b0;
            float v11 = acc[mt][nt][3] * a1 + b1;
            if (MODE == 0) {
                if (r0 < NN)
                    *(float2*)(Cf + (size_t)r0 * PITCH + c) =
                        make_float2(fmaxf(v00, 0.f), fmaxf(v01, 0.f));
                if (r0 + 8 < NN)
                    *(float2*)(Cf + (size_t)(r0 + 8) * PITCH + c) =
                        make_float2(fmaxf(v10, 0.f), fmaxf(v11, 0.f));
            } else {
                float t00 = tanhf(v00), t01 = tanhf(v01);
                float t10 = tanhf(v10), t11 = tanhf(v11);
                if (r0 < NN) {
                    *(float2*)(Cf + (size_t)r0 * PITCH + c) = make_float2(t00, t01);
                    if (Zinit)
                        *(float2*)(Zinit + (size_t)r0 * PITCH + c) =
                            make_float2(sc * t00, sc * t01);
                }
                if (r0 + 8 < NN) {
                    *(float2*)(Cf + (size_t)(r0 + 8) * PITCH + c) = make_float2(t10, t11);
                    if (Zinit)
                        *(float2*)(Zinit + (size_t)(r0 + 8) * PITCH + c) =
                            make_float2(sc * t10, sc * t11);
                }
            }
        }
    }
}

// ================= pooling + final projection (atomic-free) =================

__device__ __forceinline__ int lower_bound_batch(const int* __restrict__ b, int val) {
    int lo = 0, hi = NN;
    while (lo < hi) {
        int mid = (lo + hi) >> 1;
        if (b[mid] < val) lo = mid + 1; else hi = mid;
    }
    return lo;
}

__global__ __launch_bounds__(256) void pool_out_kernel(
    const float* __restrict__ h, const int* __restrict__ batch,
    const float* __restrict__ w, const float* __restrict__ b,
    float* __restrict__ out) {
    int g   = blockIdx.x;
    int tid = threadIdx.x;
    int lo = lower_bound_batch(batch, g);
    int hi = lower_bound_batch(batch, g + 1);
    float invc = 1.0f / fmaxf((float)(hi - lo), 1.0f);
    float part = 0.0f;
    for (int f = tid; f < DD; f += 256) {
        float mx = -INFINITY, sm = 0.0f;
        for (int node = lo; node < hi; node++) {
            float v = h[(size_t)node * PITCH + f];
            mx = fmaxf(mx, v);
            sm += v;
        }
        if (hi == lo) mx = 0.0f;
        part += mx * w[f] + sm * invc * w[DD + f];
    }
#pragma unroll
    for (int o = 16; o > 0; o >>= 1) part += __shfl_down_sync(0xffffffffu, part, o);
    __shared__ float sh[8];
    if ((tid & 31) == 0) sh[tid >> 5] = part;
    __syncthreads();
    if (tid == 0) {
        float t = 0.0f;
#pragma unroll
        for (int i = 0; i < 8; i++) t += sh[i];
        out[g] = t + b[0];
    }
}

// ================= host orchestration =================

static inline int ceil_div(int a, int b) { return (a + b - 1) / b; }

extern "C" void kernel_launch(void* const* d_in, const int* in_sizes, int n_in,
                              void* d_out, int out_size) {
    const float* x     = (const float*)d_in[0];
    const int*   ei    = (const int*)d_in[1];
    const int*   src   = ei;
    const int*   dst   = ei + EE;
    const int*   batch = (const int*)d_in[2];
    int base = (in_sizes[3] == 1) ? 4 : 3;

    const float* mlp1_w1   = (const float*)d_in[base + 0];
    const float* mlp1_b1   = (const float*)d_in[base + 1];
    const float* mlp1_bn_g = (const float*)d_in[base + 2];
    const float* mlp1_bn_b = (const float*)d_in[base + 3];
    const float* mlp1_bn_m = (const float*)d_in[base + 4];
    const float* mlp1_bn_v = (const float*)d_in[base + 5];
    const float* mlp1_w2   = (const float*)d_in[base + 6];
    const float* mlp1_b2   = (const float*)d_in[base + 7];
    const float* mlp2_w1   = (const float*)d_in[base + 8];
    const float* mlp2_b1   = (const float*)d_in[base + 9];
    const float* mlp2_bn_g = (const float*)d_in[base + 10];
    const float* mlp2_bn_b = (const float*)d_in[base + 11];
    const float* mlp2_bn_m = (const float*)d_in[base + 12];
    const float* mlp2_bn_v = (const float*)d_in[base + 13];
    const float* mlp2_w2   = (const float*)d_in[base + 14];
    const float* mlp2_b2   = (const float*)d_in[base + 15];
    const float* out1_w    = (const float*)d_in[base + 16];
    const float* out1_b    = (const float*)d_in[base + 17];
    const float* out2_w    = (const float*)d_in[base + 18];
    const float* out2_b    = (const float*)d_in[base + 19];
    const float* out3_w    = (const float*)d_in[base + 20];
    const float* out3_b    = (const float*)d_in[base + 21];
    const float* out_w     = (const float*)d_in[base + 22];
    const float* out_b     = (const float*)d_in[base + 23];
    const float* eps1      = (const float*)d_in[base + 24];
    const float* eps2      = (const float*)d_in[base + 25];
    const float* eps3      = (const float*)d_in[base + 26];

    float* out = (float*)d_out;

    float *bufA, *bufB, *bufC, *z1, *alpha1, *beta1, *alpha2, *beta2;
    __half* wh;
    cudaGetSymbolAddress((void**)&bufA, g_bufA);
    cudaGetSymbolAddress((void**)&bufB, g_bufB);
    cudaGetSymbolAddress((void**)&bufC, g_bufC);
    cudaGetSymbolAddress((void**)&z1,   g_z1);
    cudaGetSymbolAddress((void**)&alpha1, g_alpha1);
    cudaGetSymbolAddress((void**)&beta1,  g_beta1);
    cudaGetSymbolAddress((void**)&alpha2, g_alpha2);
    cudaGetSymbolAddress((void**)&beta2,  g_beta2);
    cudaGetSymbolAddress((void**)&wh, g_Wh);

    cudaFuncSetAttribute(gemm_hmma_kernel<0>,
                         cudaFuncAttributeMaxDynamicSharedMemorySize, GSMEM);
    cudaFuncSetAttribute(gemm_hmma_kernel<1>,
                         cudaFuncAttributeMaxDynamicSharedMemorySize, GSMEM);

    dim3 ggrid(ceil_div(NN, BM), 2);   // (782, 2) = 1564 CTAs
    size_t wmat = (size_t)DD * WPITCH;

    // 1: fused setup
    setup_kernel<<<ceil_div(SETUP_TOTAL, 256), 256>>>(
        mlp1_w1, mlp1_w2, mlp2_w1, mlp2_w2, out1_w, out2_w, out3_w,
        mlp1_b1, mlp1_bn_g, mlp1_bn_b, mlp1_bn_m, mlp1_bn_v,
        mlp2_b1, mlp2_bn_g, mlp2_bn_b, mlp2_bn_m, mlp2_bn_v);

    // ---------- layer 1 ----------
    pad_scale_kernel<<<ceil_div(NN * XPITCH, 256), 256>>>(x, eps1);
    scatter_add_x_kernel<<<ceil_div(EE * (XPITCH / 4), 256), 256>>>(src, dst);
    gemm_hmma_kernel<0><<<ggrid, GTHREADS, GSMEM>>>(z1, XPITCH, 3, wh + 0 * wmat,
                                                    alpha1, beta1, bufA, nullptr, nullptr);
    gemm_hmma_kernel<0><<<ggrid, GTHREADS, GSMEM>>>(bufA, PITCH, 13, wh + 1 * wmat,
                                                    nullptr, mlp1_b2, bufB, nullptr, nullptr);
    // tanh: h1 -> bufA, (1+eps2)*h1 -> bufC
    gemm_hmma_kernel<1><<<ggrid, GTHREADS, GSMEM>>>(bufB, PITCH, 13, wh + 4 * wmat,
                                                    nullptr, out1_b, bufA, eps2, bufC);
    // ---------- layer 2 ----------
    scatter_add4_kernel<<<ceil_div(EE * (DD / 4), 256), 256>>>(bufA, src, dst, bufC);
    gemm_hmma_kernel<0><<<ggrid, GTHREADS, GSMEM>>>(bufC, PITCH, 13, wh + 2 * wmat,
                                                    alpha2, beta2, bufB, nullptr, nullptr);
    gemm_hmma_kernel<0><<<ggrid, GTHREADS, GSMEM>>>(bufB, PITCH, 13, wh + 3 * wmat,
                                                    nullptr, mlp2_b2, bufA, nullptr, nullptr);
    // tanh: h2 -> bufB, (1+eps3)*h2 -> bufC
    gemm_hmma_kernel<1><<<ggrid, GTHREADS, GSMEM>>>(bufA, PITCH, 13, wh + 5 * wmat,
                                                    nullptr, out2_b, bufB, eps3, bufC);
    // ---------- layer 3 ----------
    scatter_add4_kernel<<<ceil_div(EE * (DD / 4), 256), 256>>>(bufB, src, dst, bufC);
    gemm_hmma_kernel<0><<<ggrid, GTHREADS, GSMEM>>>(bufC, PITCH, 13, wh + 2 * wmat,
                                                    alpha2, beta2, bufA, nullptr, nullptr);
    gemm_hmma_kernel<0><<<ggrid, GTHREADS, GSMEM>>>(bufA, PITCH, 13, wh + 3 * wmat,
                                                    nullptr, mlp2_b2, bufB, nullptr, nullptr);
    gemm_hmma_kernel<1><<<ggrid, GTHREADS, GSMEM>>>(bufB, PITCH, 13, wh + 6 * wmat,
                                                    nullptr, out3_b, bufA, nullptr, nullptr);
    // ---------- pooling + output ----------
    pool_out_kernel<<<GG, 256>>>(bufA, batch, out_w, out_b, out);
    (void)n_in; (void)out_size;
}

// round 11
// speedup vs baseline: 1.2595x; 1.0426x over previous
#include <cuda_runtime.h>
#include <cuda_fp16.h>
#include <cstdint>
#include <math.h>

// ================= problem constants =================
#define NN    50000
#define EE    400000
#define GG    256
#define FIN   79
#define DD    400
#define BN_EPS 1e-5f

#define NMATS  7
#define WPITCH 416            // staged weight K pitch (halfs)
#define PITCH  416            // fp32 activation pitch (13 * 32)
#define XPITCH 96             // layer-1 fp32 pitch (3 * 32)

// ================= scratch (device globals; zero-initialized) ============
__device__ float g_bufA[(size_t)NN * PITCH];
__device__ float g_bufB[(size_t)NN * PITCH];
__device__ float g_bufC[(size_t)NN * PITCH];
__device__ float g_xpad[(size_t)NN * XPITCH];
__device__ float g_z1[(size_t)NN * XPITCH];
__device__ __align__(16) __half g_Wh[(size_t)NMATS * DD * WPITCH];
__device__ float g_alpha1[DD], g_beta1[DD], g_alpha2[DD], g_beta2[DD];

// ================= helpers =================
__device__ __forceinline__ uint32_t smem_to_u32(const void* p) {
    uint32_t a;
    asm("{ .reg .u64 t; cvta.to.shared.u64 t, %1; cvt.u32.u64 %0, t; }"
        : "=r"(a) : "l"(p));
    return a;
}

__device__ __forceinline__ void cp16(uint32_t saddr, const void* gptr, bool valid) {
    int sz = valid ? 16 : 0;
    asm volatile("cp.async.cg.shared.global [%0], [%1], 16, %2;"
                 :: "r"(saddr), "l"(gptr), "r"(sz));
}
#define CP_COMMIT() asm volatile("cp.async.commit_group;")
#define CP_WAIT(n)  asm volatile("cp.async.wait_group %0;" :: "n"(n))

#define LDSM4(R, addr) \
    asm volatile("ldmatrix.sync.aligned.m8n8.x4.shared.b16 {%0,%1,%2,%3}, [%4];" \
        : "=r"((R)[0]), "=r"((R)[1]), "=r"((R)[2]), "=r"((R)[3]) : "r"(addr))

#define LDSM4P(r0, r1, r2, r3, addr) \
    asm volatile("ldmatrix.sync.aligned.m8n8.x4.shared.b16 {%0,%1,%2,%3}, [%4];" \
        : "=r"(r0), "=r"(r1), "=r"(r2), "=r"(r3) : "r"(addr))

#define LDSM2(R, addr) \
    asm volatile("ldmatrix.sync.aligned.m8n8.x2.shared.b16 {%0,%1}, [%2];" \
        : "=r"((R)[0]), "=r"((R)[1]) : "r"(addr))

__device__ __forceinline__ void mma_f16(float* d, const uint32_t* a, const uint32_t* b) {
    asm volatile(
        "mma.sync.aligned.m16n8k16.row.col.f32.f16.f16.f32 "
        "{%0,%1,%2,%3}, {%4,%5,%6,%7}, {%8,%9}, {%0,%1,%2,%3};"
        : "+f"(d[0]), "+f"(d[1]), "+f"(d[2]), "+f"(d[3])
        : "r"(a[0]), "r"(a[1]), "r"(a[2]), "r"(a[3]), "r"(b[0]), "r"(b[1]));
}

__device__ __forceinline__ uint32_t pack_h2(__half x, __half y) {
    return ((uint32_t)*(uint16_t*)&y << 16) | *(uint16_t*)&x;
}

__device__ __forceinline__ void red_add_v4(float* p, float4 v) {
    asm volatile("red.global.add.v4.f32 [%0], {%1, %2, %3, %4};"
                 :: "l"(p), "f"(v.x), "f"(v.y), "f"(v.z), "f"(v.w) : "memory");
}

// ================= fused setup kernel =================
#define T1 (NMATS * DD * WPITCH)
#define SETUP_TOTAL (T1 + 800 + NN * 48)

__global__ void setup_kernel(
    const float* __restrict__ w0, const float* __restrict__ w1,
    const float* __restrict__ w2, const float* __restrict__ w3,
    const float* __restrict__ w4, const float* __restrict__ w5,
    const float* __restrict__ w6,
    const float* __restrict__ b1a, const float* __restrict__ g1,
    const float* __restrict__ bb1, const float* __restrict__ m1,
    const float* __restrict__ v1,
    const float* __restrict__ b1b, const float* __restrict__ g2,
    const float* __restrict__ bb2, const float* __restrict__ m2,
    const float* __restrict__ v2) {
    int idx = blockIdx.x * blockDim.x + threadIdx.x;
    if (idx < T1) {
        const int per_mat = DD * WPITCH;
        int m = idx / per_mat;
        int r = idx - m * per_mat;
        int n = r / WPITCH;
        int k = r - n * WPITCH;
        int Km = (m == 0) ? FIN : DD;
        const float* W;
        switch (m) {
            case 0: W = w0; break; case 1: W = w1; break; case 2: W = w2; break;
            case 3: W = w3; break; case 4: W = w4; break; case 5: W = w5; break;
            default: W = w6; break;
        }
        float val = (k < Km) ? W[(size_t)k * DD + n] : 0.0f;
        g_Wh[idx] = __float2half(val);
    } else if (idx < T1 + 800) {
        int j = idx - T1;
        if (j < DD) {
            float a = g1[j] * rsqrtf(v1[j] + BN_EPS);
            g_alpha1[j] = a;
            g_beta1[j]  = (b1a[j] - m1[j]) * a + bb1[j];
        } else {
            int c = j - DD;
            float a = g2[c] * rsqrtf(v2[c] + BN_EPS);
            g_alpha2[c] = a;
            g_beta2[c]  = (b1b[c] - m2[c]) * a + bb2[c];
        }
    } else if (idx < SETUP_TOTAL) {
        int j = idx - T1 - 800;
        int row = j / 48;
        int t = j - row * 48;
        if (t < 16)      g_bufA[(size_t)row * PITCH + DD + t] = 0.0f;
        else if (t < 32) g_bufB[(size_t)row * PITCH + DD + (t - 16)] = 0.0f;
        else             g_bufC[(size_t)row * PITCH + DD + (t - 32)] = 0.0f;
    }
}

// ================= layer-1 glue =================

__global__ void pad_scale_kernel(const float* __restrict__ x,
                                 const float* __restrict__ eps) {
    int idx = blockIdx.x * blockDim.x + threadIdx.x;
    if (idx >= NN * XPITCH) return;
    int row = idx / XPITCH;
    int col = idx - row * XPITCH;
    float v = (col < FIN) ? x[(size_t)row * FIN + col] : 0.0f;
    g_xpad[idx] = v;
    g_z1[idx]   = (1.0f + eps[0]) * v;
}

__global__ void scatter_add_x_kernel(const int* __restrict__ src,
                                     const int* __restrict__ dst) {
    int idx = blockIdx.x * blockDim.x + threadIdx.x;
    if (idx >= EE * (XPITCH / 4)) return;
    int e = idx / (XPITCH / 4);
    int q = idx - e * (XPITCH / 4);
    const float4 v = *(const float4*)(g_xpad + (size_t)src[e] * XPITCH + q * 4);
    red_add_v4(g_z1 + (size_t)dst[e] * XPITCH + q * 4, v);
}

__global__ void scatter_add4_kernel(const float* __restrict__ h,
                                    const int* __restrict__ src,
                                    const int* __restrict__ dst,
                                    float* __restrict__ z) {
    int idx = blockIdx.x * blockDim.x + threadIdx.x;
    if (idx >= EE * (DD / 4)) return;
    int e = idx / (DD / 4);
    int q = idx - e * (DD / 4);
    const float4 v = *(const float4*)(h + (size_t)src[e] * PITCH + q * 4);
    red_add_v4(z + (size_t)dst[e] * PITCH + q * 4, v);
}

// ================= HMMA GEMM: fp32 A, in-smem fp16 hi/lo split =============
// BM=64, 320 threads, 2 CTAs/SM. ONE barrier per k-block: split of the next
// k-block's planes is overlapped with the current k-block's MMAs.
// AF/B: 3 cp.async stages. Planes: independent 2-slot double buffer.
// MODE 0: relu -> fp32 Cf.  MODE 1: tanh -> fp32 Cf (+ (1+eps)*tanh -> Zinit)
// INVARIANT: A, Cf, Zinit pairwise distinct.
#define BM 64
#define BN 200
#define GTHREADS 320
#define AF_STAGE 9216                  // fp32 A tile: 64 rows * 144B
#define AF_BASE  0                     // 3 stages: [0, 27648)
#define PL_BASE  (3 * AF_STAGE)        // 2 plane buffers (hi 5120 + lo 5120 each)
#define PL_SLOT  10240
#define PL_HI(p) (PL_BASE + (p) * PL_SLOT)
#define PL_LO(p) (PL_BASE + (p) * PL_SLOT + 5120)
#define B_BASE   (PL_BASE + 2 * PL_SLOT)   // 48128
#define B_STAGE  16000
#define GSMEM    (B_BASE + 3 * B_STAGE)    // 96128 (2 CTAs = 192256 < 228K)

__device__ __forceinline__ void load_stage(
    uint32_t sb, int st,
    const float* __restrict__ A, int lda,
    const __half* __restrict__ Wh,
    int m0, int n0, int kb, int tid) {
    int k0 = kb * 32;
    uint32_t af = sb + AF_BASE + st * AF_STAGE;
    uint32_t bb = sb + B_BASE + st * B_STAGE;
#pragma unroll 1
    for (int id = tid; id < 1312; id += GTHREADS) {
        if (id < 512) {
            int row = id >> 3, ch = id & 7;
            int gr = m0 + row;
            bool valid = gr < NN;
            size_t goff = valid ? ((size_t)gr * lda + k0 + ch * 4) : 0;
            cp16(af + row * 144 + ch * 16, A + goff, valid);
        } else {
            int id2 = id - 512;
            int row = id2 >> 2, ch = id2 & 3;
            size_t goff = (size_t)(n0 + row) * WPITCH + k0 + ch * 8;
            cp16(bb + row * 80 + ch * 16, Wh + goff, true);
        }
    }
}

// split AF stage st -> plane buffer p
__device__ __forceinline__ void split_tile(char* smem, int st, int p, int tid) {
    if (tid < 256) {
        char* af = smem + AF_BASE + st * AF_STAGE;
        int row = tid >> 2, ch = tid & 3;
        const float4 v0 = *(const float4*)(af + row * 144 + ch * 32);
        const float4 v1 = *(const float4*)(af + row * 144 + ch * 32 + 16);
        float f[8] = {v0.x, v0.y, v0.z, v0.w, v1.x, v1.y, v1.z, v1.w};
        uint32_t hp[4], lp[4];
#pragma unroll
        for (int j = 0; j < 4; j++) {
            __half h0 = __float2half(f[2 * j]);
            __half h1 = __float2half(f[2 * j + 1]);
            __half l0 = __float2half(f[2 * j]     - __half2float(h0));
            __half l1 = __float2half(f[2 * j + 1] - __half2float(h1));
            hp[j] = pack_h2(h0, h1);
            lp[j] = pack_h2(l0, l1);
        }
        *(uint4*)(smem + PL_HI(p) + row * 80 + ch * 16) = make_uint4(hp[0], hp[1], hp[2], hp[3]);
        *(uint4*)(smem + PL_LO(p) + row * 80 + ch * 16) = make_uint4(lp[0], lp[1], lp[2], lp[3]);
    }
}

template <int MODE>
__global__ __launch_bounds__(GTHREADS, 2) void gemm_hmma_kernel(
    const float* __restrict__ A, int lda, int kblks,
    const __half* __restrict__ Wh,
    const float* __restrict__ alpha, const float* __restrict__ beta,
    float* __restrict__ Cf,
    const float* __restrict__ epsn, float* __restrict__ Zinit) {
    extern __shared__ char smem[];
    uint32_t sb = smem_to_u32(smem);
    int tid  = threadIdx.x;
    int wid  = tid >> 5;
    int lane = tid & 31;
    int wm = wid / 5;            // 0..1
    int wn = wid - wm * 5;       // 0..4
    int m0 = blockIdx.x * BM;
    int n0 = blockIdx.y * BN;

    float acc[2][5][4];
#pragma unroll
    for (int i = 0; i < 2; i++)
#pragma unroll
        for (int j = 0; j < 5; j++)
#pragma unroll
            for (int k = 0; k < 4; k++) acc[i][j][k] = 0.0f;

    // prologue: load stages 0,1; split stage 0 into plane 0.
    load_stage(sb, 0, A, lda, Wh, m0, n0, 0, tid);
    CP_COMMIT();
    load_stage(sb, 1, A, lda, Wh, m0, n0, 1, tid);
    CP_COMMIT();
    CP_WAIT(1);
    __syncthreads();                    // publish AF0/B0
    split_tile(smem, 0, 0, tid);        // published by iter-0 barrier

#pragma unroll 1
    for (int kb = 0; kb < kblks; kb++) {
        CP_WAIT(0);        // group kb+1 complete (only outstanding group)
        __syncthreads();   // publish cp.async data + split(kb); fence reuse
        if (kb + 2 < kblks) {
            load_stage(sb, (kb + 2) % 3, A, lda, Wh, m0, n0, kb + 2, tid);
            CP_COMMIT();
        }
        if (kb + 1 < kblks)
            split_tile(smem, (kb + 1) % 3, (kb + 1) & 1, tid);

        uint32_t ph = sb + PL_HI(kb & 1);
        uint32_t bb = sb + B_BASE + (kb % 3) * B_STAGE;
#pragma unroll
        for (int kk = 0; kk < 2; kk++) {
            uint32_t af[2][2][4];   // [plane][mtile][4]
#pragma unroll
            for (int mt = 0; mt < 2; mt++) {
                uint32_t row  = wm * 32 + mt * 16 + (lane & 15);
                uint32_t addr = ph + row * 80 + kk * 32 + ((lane >> 4) << 4);
                LDSM4(af[0][mt], addr);
                LDSM4(af[1][mt], addr + 5120);   // lo plane
            }
            uint32_t bfr[5][2];
            {
                int l8  = lane & 7;
                int grp = lane >> 3;           // 0..3
#pragma unroll
                for (int pr = 0; pr < 2; pr++) {
                    uint32_t rowB = wn * 40 + pr * 16 + (grp >> 1) * 8 + l8;
                    uint32_t addr = bb + rowB * 80 + kk * 32 + ((grp & 1) << 4);
                    LDSM4P(bfr[2 * pr][0], bfr[2 * pr][1],
                           bfr[2 * pr + 1][0], bfr[2 * pr + 1][1], addr);
                }
                uint32_t rowB = wn * 40 + 32 + l8;
                uint32_t addr = bb + rowB * 80 + kk * 32 + (((lane >> 3) & 1) << 4);
                LDSM2(bfr[4], addr);
            }
#pragma unroll
            for (int mt = 0; mt < 2; mt++)
#pragma unroll
                for (int nt = 0; nt < 5; nt++) {
                    mma_f16(acc[mt][nt], af[0][mt], bfr[nt]);  // Ah * W
                    mma_f16(acc[mt][nt], af[1][mt], bfr[nt]);  // Al * W
                }
        }
    }

    // ---------------- epilogue ----------------
    float sc = (MODE == 1 && Zinit) ? (1.0f + epsn[0]) : 0.0f;
#pragma unroll
    for (int mt = 0; mt < 2; mt++) {
#pragma unroll
        for (int nt = 0; nt < 5; nt++) {
            int c  = n0 + wn * 40 + nt * 8 + (lane & 3) * 2;
            int r0 = m0 + wm * 32 + mt * 16 + (lane >> 2);
            float a0 = alpha ? alpha[c]     : 1.0f;
            float a1 = alpha ? alpha[c + 1] : 1.0f;
            float b0 = beta[c], b1 = beta[c + 1];
            float v00 = acc[mt][nt][0] * a0 + b0;
            float v01 = acc[mt][nt][1] * a1 + b1;
            float v10 = acc[mt][nt][2] * a0 + b0;
            float v11 = acc[mt][nt][3] * a1 + b1;
            if (MODE == 0) {
                if (r0 < NN)
                    *(float2*)(Cf + (size_t)r0 * PITCH + c) =
                        make_float2(fmaxf(v00, 0.f), fmaxf(v01, 0.f));
                if (r0 + 8 < NN)
                    *(float2*)(Cf + (size_t)(r0 + 8) * PITCH + c) =
                        make_float2(fmaxf(v10, 0.f), fmaxf(v11, 0.f));
            } else {
                float t00 = tanhf(v00), t01 = tanhf(v01);
                float t10 = tanhf(v10), t11 = tanhf(v11);
                if (r0 < NN) {
                    *(float2*)(Cf + (size_t)r0 * PITCH + c) = make_float2(t00, t01);
                    if (Zinit)
                        *(float2*)(Zinit + (size_t)r0 * PITCH + c) =
                            make_float2(sc * t00, sc * t01);
                }
                if (r0 + 8 < NN) {
                    *(float2*)(Cf + (size_t)(r0 + 8) * PITCH + c) = make_float2(t10, t11);
                    if (Zinit)
                        *(float2*)(Zinit + (size_t)(r0 + 8) * PITCH + c) =
                            make_float2(sc * t10, sc * t11);
                }
            }
        }
    }
}

// ================= pooling + final projection (atomic-free) =================

__device__ __forceinline__ int lower_bound_batch(const int* __restrict__ b, int val) {
    int lo = 0, hi = NN;
    while (lo < hi) {
        int mid = (lo + hi) >> 1;
        if (b[mid] < val) lo = mid + 1; else hi = mid;
    }
    return lo;
}

__global__ __launch_bounds__(256) void pool_out_kernel(
    const float* __restrict__ h, const int* __restrict__ batch,
    const float* __restrict__ w, const float* __restrict__ b,
    float* __restrict__ out) {
    int g   = blockIdx.x;
    int tid = threadIdx.x;
    int lo = lower_bound_batch(batch, g);
    int hi = lower_bound_batch(batch, g + 1);
    float invc = 1.0f / fmaxf((float)(hi - lo), 1.0f);
    float part = 0.0f;
    for (int f = tid; f < DD; f += 256) {
        float mx = -INFINITY, sm = 0.0f;
        for (int node = lo; node < hi; node++) {
            float v = h[(size_t)node * PITCH + f];
            mx = fmaxf(mx, v);
            sm += v;
        }
        if (hi == lo) mx = 0.0f;
        part += mx * w[f] + sm * invc * w[DD + f];
    }
#pragma unroll
    for (int o = 16; o > 0; o >>= 1) part += __shfl_down_sync(0xffffffffu, part, o);
    __shared__ float sh[8];
    if ((tid & 31) == 0) sh[tid >> 5] = part;
    __syncthreads();
    if (tid == 0) {
        float t = 0.0f;
#pragma unroll
        for (int i = 0; i < 8; i++) t += sh[i];
        out[g] = t + b[0];
    }
}

// ================= host orchestration =================

static inline int ceil_div(int a, int b) { return (a + b - 1) / b; }

extern "C" void kernel_launch(void* const* d_in, const int* in_sizes, int n_in,
                              void* d_out, int out_size) {
    const float* x     = (const float*)d_in[0];
    const int*   ei    = (const int*)d_in[1];
    const int*   src   = ei;
    const int*   dst   = ei + EE;
    const int*   batch = (const int*)d_in[2];
    int base = (in_sizes[3] == 1) ? 4 : 3;

    const float* mlp1_w1   = (const float*)d_in[base + 0];
    const float* mlp1_b1   = (const float*)d_in[base + 1];
    const float* mlp1_bn_g = (const float*)d_in[base + 2];
    const float* mlp1_bn_b = (const float*)d_in[base + 3];
    const float* mlp1_bn_m = (const float*)d_in[base + 4];
    const float* mlp1_bn_v = (const float*)d_in[base + 5];
    const float* mlp1_w2   = (const float*)d_in[base + 6];
    const float* mlp1_b2   = (const float*)d_in[base + 7];
    const float* mlp2_w1   = (const float*)d_in[base + 8];
    const float* mlp2_b1   = (const float*)d_in[base + 9];
    const float* mlp2_bn_g = (const float*)d_in[base + 10];
    const float* mlp2_bn_b = (const float*)d_in[base + 11];
    const float* mlp2_bn_m = (const float*)d_in[base + 12];
    const float* mlp2_bn_v = (const float*)d_in[base + 13];
    const float* mlp2_w2   = (const float*)d_in[base + 14];
    const float* mlp2_b2   = (const float*)d_in[base + 15];
    const float* out1_w    = (const float*)d_in[base + 16];
    const float* out1_b    = (const float*)d_in[base + 17];
    const float* out2_w    = (const float*)d_in[base + 18];
    const float* out2_b    = (const float*)d_in[base + 19];
    const float* out3_w    = (const float*)d_in[base + 20];
    const float* out3_b    = (const float*)d_in[base + 21];
    const float* out_w     = (const float*)d_in[base + 22];
    const float* out_b     = (const float*)d_in[base + 23];
    const float* eps1      = (const float*)d_in[base + 24];
    const float* eps2      = (const float*)d_in[base + 25];
    const float* eps3      = (const float*)d_in[base + 26];

    float* out = (float*)d_out;

    float *bufA, *bufB, *bufC, *z1, *alpha1, *beta1, *alpha2, *beta2;
    __half* wh;
    cudaGetSymbolAddress((void**)&bufA, g_bufA);
    cudaGetSymbolAddress((void**)&bufB, g_bufB);
    cudaGetSymbolAddress((void**)&bufC, g_bufC);
    cudaGetSymbolAddress((void**)&z1,   g_z1);
    cudaGetSymbolAddress((void**)&alpha1, g_alpha1);
    cudaGetSymbolAddress((void**)&beta1,  g_beta1);
    cudaGetSymbolAddress((void**)&alpha2, g_alpha2);
    cudaGetSymbolAddress((void**)&beta2,  g_beta2);
    cudaGetSymbolAddress((void**)&wh, g_Wh);

    cudaFuncSetAttribute(gemm_hmma_kernel<0>,
                         cudaFuncAttributeMaxDynamicSharedMemorySize, GSMEM);
    cudaFuncSetAttribute(gemm_hmma_kernel<1>,
                         cudaFuncAttributeMaxDynamicSharedMemorySize, GSMEM);

    dim3 ggrid(ceil_div(NN, BM), 2);   // (782, 2) = 1564 CTAs
    size_t wmat = (size_t)DD * WPITCH;

    // 1: fused setup
    setup_kernel<<<ceil_div(SETUP_TOTAL, 256), 256>>>(
        mlp1_w1, mlp1_w2, mlp2_w1, mlp2_w2, out1_w, out2_w, out3_w,
        mlp1_b1, mlp1_bn_g, mlp1_bn_b, mlp1_bn_m, mlp1_bn_v,
        mlp2_b1, mlp2_bn_g, mlp2_bn_b, mlp2_bn_m, mlp2_bn_v);

    // ---------- layer 1 ----------
    pad_scale_kernel<<<ceil_div(NN * XPITCH, 256), 256>>>(x, eps1);
    scatter_add_x_kernel<<<ceil_div(EE * (XPITCH / 4), 256), 256>>>(src, dst);
    gemm_hmma_kernel<0><<<ggrid, GTHREADS, GSMEM>>>(z1, XPITCH, 3, wh + 0 * wmat,
                                                    alpha1, beta1, bufA, nullptr, nullptr);
    gemm_hmma_kernel<0><<<ggrid, GTHREADS, GSMEM>>>(bufA, PITCH, 13, wh + 1 * wmat,
                                                    nullptr, mlp1_b2, bufB, nullptr, nullptr);
    // tanh: h1 -> bufA, (1+eps2)*h1 -> bufC
    gemm_hmma_kernel<1><<<ggrid, GTHREADS, GSMEM>>>(bufB, PITCH, 13, wh + 4 * wmat,
                                                    nullptr, out1_b, bufA, eps2, bufC);
    // ---------- layer 2 ----------
    scatter_add4_kernel<<<ceil_div(EE * (DD / 4), 256), 256>>>(bufA, src, dst, bufC);
    gemm_hmma_kernel<0><<<ggrid, GTHREADS, GSMEM>>>(bufC, PITCH, 13, wh + 2 * wmat,
                                                    alpha2, beta2, bufB, nullptr, nullptr);
    gemm_hmma_kernel<0><<<ggrid, GTHREADS, GSMEM>>>(bufB, PITCH, 13, wh + 3 * wmat,
                                                    nullptr, mlp2_b2, bufA, nullptr, nullptr);
    // tanh: h2 -> bufB, (1+eps3)*h2 -> bufC
    gemm_hmma_kernel<1><<<ggrid, GTHREADS, GSMEM>>>(bufA, PITCH, 13, wh + 5 * wmat,
                                                    nullptr, out2_b, bufB, eps3, bufC);
    // ---------- layer 3 ----------
    scatter_add4_kernel<<<ceil_div(EE * (DD / 4), 256), 256>>>(bufB, src, dst, bufC);
    gemm_hmma_kernel<0><<<ggrid, GTHREADS, GSMEM>>>(bufC, PITCH, 13, wh + 2 * wmat,
                                                    alpha2, beta2, bufA, nullptr, nullptr);
    gemm_hmma_kernel<0><<<ggrid, GTHREADS, GSMEM>>>(bufA, PITCH, 13, wh + 3 * wmat,
                                                    nullptr, mlp2_b2, bufB, nullptr, nullptr);
    gemm_hmma_kernel<1><<<ggrid, GTHREADS, GSMEM>>>(bufB, PITCH, 13, wh + 6 * wmat,
                                                    nullptr, out3_b, bufA, nullptr, nullptr);
    // ---------- pooling + output ----------
    pool_out_kernel<<<GG, 256>>>(bufA, batch, out_w, out_b, out);
    (void)n_in; (void)out_size;
}